// round 9
// baseline (speedup 1.0000x reference)
#include <cuda_runtime.h>
#include <cuda_bf16.h>
#include <math.h>
#include <stdint.h>

// ---------------- problem constants ----------------
#define B_      128
#define STREAM_ 512
#define INCH    4
#define EXTRA_  5
#define G_      2
#define STEP_   16
#define SIGC    1110        // C + C^2 + C^3, C=10
#define W_      31          // windows
#define F_      2220        // GROUPS * SIGC
#define RNN_    256
#define OUT_    10
#define KP2     2240        // F_ padded to multiple of 64 (bf16 chunk)
#define MROWS   (W_ * B_)   // 3968
#define NGI     768         // 3 * RNN
#define NC      (KP2 / 64)  // 35 K-chunks of 64 bf16 (128 bytes)

// ---------------- device scratch (static, allowed) ----------------
__device__ __nv_bfloat16 g_A0[MROWS * KP2];   // sig hi  (~17.8 MB)
__device__ __nv_bfloat16 g_A1[MROWS * KP2];   // sig lo
__device__ __nv_bfloat16 g_B0[NGI * KP2];     // W_ih hi (~3.4 MB)
__device__ __nv_bfloat16 g_B1[NGI * KP2];     // W_ih lo
__device__ float g_gi[MROWS * NGI];           // ~12 MB

// ---------------- PTX helpers (portable: sm_80/90 class only) ----------------
__device__ __forceinline__ uint32_t smem_u32(const void* p) {
    uint32_t a;
    asm("{ .reg .u64 t; cvta.to.shared.u64 t, %1; cvt.u32.u64 %0, t; }" : "=r"(a) : "l"(p));
    return a;
}

__device__ __forceinline__ uint32_t swz(uint32_t off) { return off ^ ((off >> 3) & 0x70); }

#define LDSM4(r0, r1, r2, r3, addr)                                               \
    asm volatile("ldmatrix.sync.aligned.m8n8.x4.shared.b16 {%0,%1,%2,%3}, [%4];"  \
        : "=r"(r0), "=r"(r1), "=r"(r2), "=r"(r3) : "r"(addr))

// D += A(16x16) * B(16x8), bf16 in, fp32 accum. row.col = both K-contiguous.
#define MMA16816(d, a, b0v, b1v)                                                  \
    asm volatile("mma.sync.aligned.m16n8k16.row.col.f32.bf16.bf16.f32 "           \
        "{%0,%1,%2,%3}, {%4,%5,%6,%7}, {%8,%9}, {%0,%1,%2,%3};"                   \
        : "+f"((d)[0]), "+f"((d)[1]), "+f"((d)[2]), "+f"((d)[3])                  \
        : "r"((a)[0]), "r"((a)[1]), "r"((a)[2]), "r"((a)[3]), "r"(b0v), "r"(b1v))

#define CLUSTER_SYNC() do {                                                       \
    asm volatile("barrier.cluster.arrive.aligned;" ::: "memory");                 \
    asm volatile("barrier.cluster.wait.aligned;" ::: "memory");                   \
} while (0)

__device__ __forceinline__ uint32_t mapa_cluster(uint32_t laddr, uint32_t rank) {
    uint32_t r;
    asm("mapa.shared::cluster.u32 %0, %1, %2;" : "=r"(r) : "r"(laddr), "r"(rank));
    return r;
}
__device__ __forceinline__ void st_cluster_f32(uint32_t addr, float v) {
    asm volatile("st.shared::cluster.f32 [%0], %1;" :: "r"(addr), "f"(v) : "memory");
}

// split fp32 -> two bf16 (hi = rn(v), lo = rn(v - hi))
__device__ __forceinline__ void store_split(size_t idx, float v,
                                            __nv_bfloat16* a0, __nv_bfloat16* a1) {
    __nv_bfloat16 h = __float2bfloat16(v);
    a0[idx] = h;
    a1[idx] = __float2bfloat16(v - __bfloat162float(h));
}

// =====================================================================
// Kernel 1: path signatures (Chen, depth 3) -> split bf16 into g_A0/g_A1
// =====================================================================
__global__ __launch_bounds__(128) void sig_kernel(
    const float* __restrict__ x,       // (128,512,4)
    const float* __restrict__ W_aug)   // (2,5,4)
{
    const int w  = blockIdx.x;
    const int bg = blockIdx.y;
    const int b  = bg >> 1;
    const int g  = bg & 1;
    const int tid = threadIdx.x;

    __shared__ __align__(16) float xs[32][4];
    __shared__ __align__(16) float dxw[31][10];

    {
        int row = tid >> 2, ch = tid & 3;
        xs[row][ch] = x[(b * STREAM_ + w * STEP_ + row) * INCH + ch];
    }
    __syncthreads();

    for (int idx = tid; idx < 31 * 10; idx += 128) {
        int j = idx / 10, c = idx % 10;
        float v;
        if (c < 4) {
            v = xs[j + 1][c] - xs[j][c];
        } else if (c == 4) {
            v = 1.0f / 511.0f;
        } else {
            int e = c - 5;
            const float* wa = W_aug + (g * EXTRA_ + e) * INCH;
            v = 0.f;
            #pragma unroll
            for (int i = 0; i < 4; i++) v += wa[i] * (xs[j + 1][i] - xs[j][i]);
        }
        dxw[j][c] = v;
    }
    __syncthreads();

    const size_t base = (size_t)(w * B_ + b) * KP2 + (size_t)g * SIGC;

    if (tid < 100) {
        const int a  = tid / 10;
        const int bb = tid % 10;
        float s1a = 0.f, s2 = 0.f;
        float s3[10];
        #pragma unroll
        for (int c = 0; c < 10; c++) s3[c] = 0.f;

        for (int j = 0; j < 31; j++) {
            float dxa = dxw[j][a];
            float dxb = dxw[j][bb];
            float factor = s2 + dxb * (0.5f * s1a + (1.0f / 6.0f) * dxa);
            #pragma unroll
            for (int c = 0; c < 10; c++) s3[c] += factor * dxw[j][c];
            s2  += dxb * (s1a + 0.5f * dxa);
            s1a += dxa;
        }
        if (bb == 0) store_split(base + a, s1a, g_A0, g_A1);
        store_split(base + 10 + tid, s2, g_A0, g_A1);
        #pragma unroll
        for (int c = 0; c < 10; c++)
            store_split(base + 110 + tid * 10 + c, s3[c], g_A0, g_A1);
    }
    // zero K-pad columns (g==1 block handles it once per row)
    if (g == 1 && tid < (KP2 - F_)) {
        size_t idx = (size_t)(w * B_ + b) * KP2 + F_ + tid;
        g_A0[idx] = __float2bfloat16(0.f);
        g_A1[idx] = __float2bfloat16(0.f);
    }
}

// =====================================================================
// Kernel 2: split+pad W_ih (768 x 2220) into g_B0/g_B1 (768 x 2240)
// =====================================================================
__global__ __launch_bounds__(256) void prep_w(const float* __restrict__ Wih)
{
    int idx = blockIdx.x * 256 + threadIdx.x;
    if (idx < NGI * KP2) {
        int n = idx / KP2, k = idx - n * KP2;
        float v = (k < F_) ? Wih[n * F_ + k] : 0.f;
        store_split((size_t)idx, v, g_B0, g_B1);
    }
}

// =====================================================================
// Kernel 3: GI = sig @ W_ih^T + b_ih via mma.sync bf16-split (3 products).
// 64x128 CTA tile (372 tiles, 2 CTAs/SM), 8 warps of 32(M)x32(N),
// K-chunk 64, double-buffered cp.async, SW128 smem, ldmatrix TN.
// =====================================================================
#define A_TILE_B    8192                   // 64 rows x 128 bytes
#define B_TILE_B    16384                  // 128 rows x 128 bytes
#define STAGE_B     (2 * A_TILE_B + 2 * B_TILE_B)   // 49152
#define GEMM_SMEM   (2 * STAGE_B)          // 98304 bytes (2 stages)

__global__ __launch_bounds__(256, 2) void gemm_mma(const float* __restrict__ bih)
{
    extern __shared__ char smem[];
    const uint32_t sb = smem_u32(smem);
    const int tid  = threadIdx.x;
    const int lane = tid & 31;
    const int wid  = tid >> 5;
    const int wm   = wid & 1;         // M offset 32*wm
    const int wn   = wid >> 1;        // 0..3 -> N offset 32*wn
    const int m0 = blockIdx.x * 64;
    const int n0 = blockIdx.y * 128;

    const __nv_bfloat16* aA0 = g_A0 + (size_t)m0 * KP2;
    const __nv_bfloat16* aA1 = g_A1 + (size_t)m0 * KP2;
    const __nv_bfloat16* bB0g = g_B0 + (size_t)n0 * KP2;
    const __nv_bfloat16* bB1g = g_B1 + (size_t)n0 * KP2;

    auto load_chunk = [&](int c) {
        uint32_t sbase = sb + (uint32_t)(c & 1) * STAGE_B;
        #pragma unroll
        for (int tt = 0; tt < 2; tt++) {
            const __nv_bfloat16* gp = tt ? aA1 : aA0;
            #pragma unroll
            for (int it = 0; it < 2; it++) {
                int i = tid + it * 256;           // 0..511
                int row = i >> 3, seg = i & 7;
                uint32_t dst = sbase + (uint32_t)tt * A_TILE_B
                             + swz((uint32_t)row * 128 + (uint32_t)seg * 16);
                const void* src = gp + (size_t)row * KP2 + (size_t)c * 64 + seg * 8;
                asm volatile("cp.async.cg.shared.global [%0], [%1], 16;\n"
                             :: "r"(dst), "l"(src));
            }
        }
        #pragma unroll
        for (int tt = 0; tt < 2; tt++) {
            const __nv_bfloat16* gp = tt ? bB1g : bB0g;
            #pragma unroll
            for (int it = 0; it < 4; it++) {
                int i = tid + it * 256;           // 0..1023
                int row = i >> 3, seg = i & 7;
                uint32_t dst = sbase + 2 * A_TILE_B + (uint32_t)tt * B_TILE_B
                             + swz((uint32_t)row * 128 + (uint32_t)seg * 16);
                const void* src = gp + (size_t)row * KP2 + (size_t)c * 64 + seg * 8;
                asm volatile("cp.async.cg.shared.global [%0], [%1], 16;\n"
                             :: "r"(dst), "l"(src));
            }
        }
        asm volatile("cp.async.commit_group;\n" ::: "memory");
    };

    float acc[2][4][4];
    #pragma unroll
    for (int i = 0; i < 2; i++)
        #pragma unroll
        for (int jj = 0; jj < 4; jj++)
            #pragma unroll
            for (int k = 0; k < 4; k++) acc[i][jj][k] = 0.f;

    const uint32_t a_row  = (uint32_t)(wm * 32 + (lane & 15));
    const uint32_t a_byte = (uint32_t)((lane >> 4) << 4);
    const uint32_t b_row  = (uint32_t)(wn * 32 + (lane & 7) + ((lane >> 4) << 3));
    const uint32_t b_byte = (uint32_t)((lane & 8) << 1);

    load_chunk(0);

    for (int c = 0; c < NC; c++) {
        if (c + 1 < NC) load_chunk(c + 1);
        if (c + 1 < NC) asm volatile("cp.async.wait_group 1;\n" ::: "memory");
        else            asm volatile("cp.async.wait_group 0;\n" ::: "memory");
        __syncthreads();

        const uint32_t stage = sb + (uint32_t)(c & 1) * STAGE_B;
        const uint32_t aB0 = stage;
        const uint32_t aB1 = stage + A_TILE_B;
        const uint32_t bB0 = stage + 2 * A_TILE_B;
        const uint32_t bB1 = stage + 2 * A_TILE_B + B_TILE_B;

        #pragma unroll
        for (int ks = 0; ks < 4; ks++) {
            const uint32_t kb = (uint32_t)ks * 32;
            uint32_t a0f[2][4], a1f[2][4];
            #pragma unroll
            for (int mt = 0; mt < 2; mt++) {
                uint32_t off = swz((a_row + mt * 16) * 128 + kb + a_byte);
                LDSM4(a0f[mt][0], a0f[mt][1], a0f[mt][2], a0f[mt][3], aB0 + off);
                LDSM4(a1f[mt][0], a1f[mt][1], a1f[mt][2], a1f[mt][3], aB1 + off);
            }
            uint32_t b0f[2][4], b1f[2][4];
            #pragma unroll
            for (int nt = 0; nt < 2; nt++) {
                uint32_t off = swz((b_row + nt * 16) * 128 + kb + b_byte);
                LDSM4(b0f[nt][0], b0f[nt][1], b0f[nt][2], b0f[nt][3], bB0 + off);
                LDSM4(b1f[nt][0], b1f[nt][1], b1f[nt][2], b1f[nt][3], bB1 + off);
            }
            #pragma unroll
            for (int mt = 0; mt < 2; mt++) {
                #pragma unroll
                for (int nt = 0; nt < 2; nt++) {
                    MMA16816(acc[mt][2 * nt],     a0f[mt], b0f[nt][0], b0f[nt][1]);
                    MMA16816(acc[mt][2 * nt + 1], a0f[mt], b0f[nt][2], b0f[nt][3]);
                    MMA16816(acc[mt][2 * nt],     a0f[mt], b1f[nt][0], b1f[nt][1]);
                    MMA16816(acc[mt][2 * nt + 1], a0f[mt], b1f[nt][2], b1f[nt][3]);
                    MMA16816(acc[mt][2 * nt],     a1f[mt], b0f[nt][0], b0f[nt][1]);
                    MMA16816(acc[mt][2 * nt + 1], a1f[mt], b0f[nt][2], b0f[nt][3]);
                }
            }
        }
        __syncthreads();
    }

    float2 bias[4];
    {
        const int nbase = n0 + wn * 32 + 2 * (lane & 3);
        #pragma unroll
        for (int nt8 = 0; nt8 < 4; nt8++) {
            bias[nt8].x = bih[nbase + nt8 * 8];
            bias[nt8].y = bih[nbase + nt8 * 8 + 1];
        }
    }
    #pragma unroll
    for (int mt = 0; mt < 2; mt++) {
        const int mlo = m0 + wm * 32 + mt * 16 + (lane >> 2);
        #pragma unroll
        for (int nt8 = 0; nt8 < 4; nt8++) {
            const int n = n0 + wn * 32 + nt8 * 8 + 2 * (lane & 3);
            float2 lo, hi;
            lo.x = acc[mt][nt8][0] + bias[nt8].x;
            lo.y = acc[mt][nt8][1] + bias[nt8].y;
            hi.x = acc[mt][nt8][2] + bias[nt8].x;
            hi.y = acc[mt][nt8][3] + bias[nt8].y;
            *(float2*)(g_gi + (size_t)mlo * NGI + n)       = lo;
            *(float2*)(g_gi + (size_t)(mlo + 8) * NGI + n) = hi;
        }
    }
}

// =====================================================================
// Kernel 4: cluster GRU. 16 clusters x 8 CTAs (256 threads each).
// Cluster owns 8 batch rows; CTA rank owns 32 gate columns.
// Thread (j_local = w*4 + lane>>3, kc = lane&7) keeps W_hh[3][32] in
// 96 registers; computes partials for 8 b-rows over its 32-k slice;
// 21-SHFL butterfly over kc lands h(b=b0+kc, j) on each thread; the
// value is written into ALL 8 cluster CTAs' smem (st.shared::cluster,
// double-buffered), then barrier.cluster. No global h, no grid barrier.
// =====================================================================
#define CLS     8
#define BT      8                       // batch rows per cluster
#define KBLK    36                      // 32 k + 4 pad (conflict-free)
#define HROW    (8 * KBLK)              // 288 floats per b row
#define HS_W    (BT * HROW)             // 2304 floats per buffer

__global__ __launch_bounds__(256, 1) void gru_cluster(
    const float* __restrict__ Whh,   // (768,256)
    const float* __restrict__ bhh,   // (768)
    const float* __restrict__ Wout,  // (10,256)
    const float* __restrict__ bout,  // (10)
    float* __restrict__ out)         // (128,10)
{
    __shared__ __align__(16) float hs[2 * HS_W];   // 18 KB double buffer

    uint32_t rank;
    asm("mov.u32 %0, %%cluster_ctarank;" : "=r"(rank));
    const int tid  = threadIdx.x;
    const int lane = tid & 31;
    const int w    = tid >> 5;
    const int jl   = w * 4 + (lane >> 3);   // j_local 0..31
    const int kc   = lane & 7;              // k-slice owner (32 floats)
    const int cid  = blockIdx.x >> 3;       // cluster id 0..15
    const int b0   = cid * BT;
    const int j    = (int)rank * 32 + jl;   // global gate column
    const int b    = b0 + kc;               // this thread's output batch row

    // ---- one-time: W_hh[3 gates][my 32-k slice] -> 96 registers ----
    float4 W4[3][8];
    #pragma unroll
    for (int g = 0; g < 3; g++)
        #pragma unroll
        for (int i2 = 0; i2 < 8; i2++)
            W4[g][i2] = *(const float4*)&Whh[(g * RNN_ + j) * RNN_ + kc * 32 + i2 * 4];

    const float br = bhh[j], bz = bhh[RNN_ + j], bn = bhh[2 * RNN_ + j];

    // zero hs[0] (hs[1] fully overwritten in step 0)
    for (int i = tid; i < HS_W; i += 256) hs[i] = 0.f;
    __syncthreads();

    // precompute peer smem base addresses (mapa once; add offsets per step)
    const uint32_t my_off = (uint32_t)(kc * HROW + (int)rank * KBLK + jl);  // words
    uint32_t base0 = smem_u32(&hs[0]);
    uint32_t peer[CLS];
    #pragma unroll
    for (int r = 0; r < CLS; r++) peer[r] = mapa_cluster(base0, (uint32_t)r);

    // h_prev read offset for (b=kc row, col j) within a buffer (words)
    const uint32_t hp_off = my_off;

    for (int t = 0; t < W_; t++) {
        const int cur = t & 1, nxt = cur ^ 1;
        const float* hb = hs + cur * HS_W;

        // gi loads for this thread's output (overlap with compute)
        const float* gi = g_gi + ((size_t)t * B_ + b) * NGI;
        float ir  = __ldcg(&gi[j]);
        float iz  = __ldcg(&gi[RNN_ + j]);
        float inn = __ldcg(&gi[2 * RNN_ + j]);

        // ---- partials: 8 b-rows over my 32-k slice (768 FMA) ----
        float acc[8][3];
        #pragma unroll
        for (int bb = 0; bb < 8; bb++) {
            const float* hr = hb + bb * HROW + kc * KBLK;
            float a0 = 0.f, a1 = 0.f, a2 = 0.f;
            #pragma unroll
            for (int i2 = 0; i2 < 8; i2++) {
                float4 h4 = *(const float4*)&hr[i2 * 4];
                a0 += W4[0][i2].x * h4.x + W4[0][i2].y * h4.y + W4[0][i2].z * h4.z + W4[0][i2].w * h4.w;
                a1 += W4[1][i2].x * h4.x + W4[1][i2].y * h4.y + W4[1][i2].z * h4.z + W4[1][i2].w * h4.w;
                a2 += W4[2][i2].x * h4.x + W4[2][i2].y * h4.y + W4[2][i2].z * h4.z + W4[2][i2].w * h4.w;
            }
            acc[bb][0] = a0; acc[bb][1] = a1; acc[bb][2] = a2;
        }

        // ---- butterfly reduce over 8 kc-lanes (21 SHFL), lands b=kc ----
        #pragma unroll
        for (int m = 4; m >= 1; m >>= 1) {
            #pragma unroll
            for (int bb = 0; bb < m; bb++) {
                #pragma unroll
                for (int g = 0; g < 3; g++) {
                    float lo = acc[bb][g], hi2 = acc[bb + m][g];
                    float send = (kc & m) ? lo  : hi2;
                    float keep = (kc & m) ? hi2 : lo;
                    acc[bb][g] = keep + __shfl_xor_sync(0xffffffffu, send, m);
                }
            }
        }

        // ---- gates for (b, j) ----
        float r = 1.f / (1.f + expf(-(ir + acc[0][0] + br)));
        float z = 1.f / (1.f + expf(-(iz + acc[0][1] + bz)));
        float n = tanhf(inn + r * (acc[0][2] + bn));
        float hprev = hb[hp_off];
        float hnew  = (1.f - z) * n + z * hprev;

        // ---- broadcast h(b,j) into all 8 cluster CTAs' hs[nxt] ----
        const uint32_t boff = (uint32_t)(nxt * HS_W + my_off) * 4u;
        #pragma unroll
        for (int rr = 0; rr < CLS; rr++)
            st_cluster_f32(peer[rr] + boff, hnew);

        CLUSTER_SYNC();   // release writes + acquire peers' writes
    }

    // ---- output head: rank 0 of each cluster, from LOCAL smem h ----
    if (rank == 0) {
        const float* hf = hs + (W_ & 1) * HS_W;   // final buffer = 1
        for (int i = tid; i < BT * OUT_; i += 256) {
            int bb = i / OUT_, o = i % OUT_;
            float s = 0.f;
            #pragma unroll 8
            for (int k = 0; k < RNN_; k++)
                s += hf[bb * HROW + (k >> 5) * KBLK + (k & 31)] * Wout[o * RNN_ + k];
            out[(b0 + bb) * OUT_ + o] = 1.f / (1.f + expf(-(s + bout[o])));
        }
    }
}

// =====================================================================
extern "C" void kernel_launch(void* const* d_in, const int* in_sizes, int n_in,
                              void* d_out, int out_size)
{
    const float* x     = (const float*)d_in[0];
    const float* W_aug = (const float*)d_in[1];
    // d_in[2] = b_aug: constant, cancels in increments
    const float* W_ih  = (const float*)d_in[3];
    const float* W_hh  = (const float*)d_in[4];
    const float* b_ih  = (const float*)d_in[5];
    const float* b_hh  = (const float*)d_in[6];
    const float* W_out = (const float*)d_in[7];
    const float* b_out = (const float*)d_in[8];
    float* out = (float*)d_out;

    cudaFuncSetAttribute(gemm_mma, cudaFuncAttributeMaxDynamicSharedMemorySize, GEMM_SMEM);

    sig_kernel<<<dim3(W_, B_ * G_), 128>>>(x, W_aug);
    prep_w<<<(NGI * KP2 + 255) / 256, 256>>>(W_ih);
    gemm_mma<<<dim3(MROWS / 64, NGI / 128), 256, GEMM_SMEM>>>(b_ih);

    // cluster launch: 16 clusters x 8 CTAs
    {
        cudaLaunchConfig_t cfg = {};
        cfg.gridDim  = dim3(B_ / BT * CLS, 1, 1);   // 128 CTAs
        cfg.blockDim = dim3(256, 1, 1);
        cfg.dynamicSmemBytes = 0;
        cfg.stream = 0;
        cudaLaunchAttribute attrs[1];
        attrs[0].id = cudaLaunchAttributeClusterDimension;
        attrs[0].val.clusterDim.x = CLS;
        attrs[0].val.clusterDim.y = 1;
        attrs[0].val.clusterDim.z = 1;
        cfg.attrs = attrs;
        cfg.numAttrs = 1;
        cudaLaunchKernelEx(&cfg, gru_cluster, W_hh, b_hh, W_out, b_out, out);
    }
}

// round 10
// speedup vs baseline: 1.1468x; 1.1468x over previous
#include <cuda_runtime.h>
#include <cuda_fp16.h>
#include <math.h>
#include <stdint.h>

// ---------------- problem constants ----------------
#define B_      128
#define STREAM_ 512
#define INCH    4
#define EXTRA_  5
#define G_      2
#define STEP_   16
#define SIGC    1110        // C + C^2 + C^3, C=10
#define W_      31          // windows
#define F_      2220        // GROUPS * SIGC
#define RNN_    256
#define OUT_    10
#define KP2     2240        // F_ padded to multiple of 64 (fp16 chunk)
#define MROWS   (W_ * B_)   // 3968
#define NGI     768         // 3 * RNN
#define NC      (KP2 / 64)  // 35 K-chunks of 64 fp16 (128 bytes)

// ---------------- device scratch (static, allowed) ----------------
__device__ __half g_A0[MROWS * KP2];          // sig hi fp16 (~17.8 MB)
__device__ __half g_A1[MROWS * KP2];          // sig lo fp16
__device__ __half g_B0[NGI * KP2];            // W_ih fp16  (~3.4 MB)
__device__ float g_gi[MROWS * NGI];           // ~12 MB
__device__ float g_h [2][B_ * RNN_];          // ping-pong hidden state

// per-bt barrier state: 8 groups, each padded to its own 128B lines
struct GBar { unsigned cnt; unsigned pad1[31]; volatile unsigned gen; unsigned pad2[31]; };
__device__ GBar g_bars[8];

// ---------------- PTX helpers (portable: sm_80/90 class only) ----------------
__device__ __forceinline__ uint32_t smem_u32(const void* p) {
    uint32_t a;
    asm("{ .reg .u64 t; cvta.to.shared.u64 t, %1; cvt.u32.u64 %0, t; }" : "=r"(a) : "l"(p));
    return a;
}

__device__ __forceinline__ uint32_t swz(uint32_t off) { return off ^ ((off >> 3) & 0x70); }

#define LDSM4(r0, r1, r2, r3, addr)                                               \
    asm volatile("ldmatrix.sync.aligned.m8n8.x4.shared.b16 {%0,%1,%2,%3}, [%4];"  \
        : "=r"(r0), "=r"(r1), "=r"(r2), "=r"(r3) : "r"(addr))

// D += A(16x16) * B(16x8), fp16 in, fp32 accum. row.col = both K-contiguous.
#define MMAH(d, a, b0v, b1v)                                                      \
    asm volatile("mma.sync.aligned.m16n8k16.row.col.f32.f16.f16.f32 "             \
        "{%0,%1,%2,%3}, {%4,%5,%6,%7}, {%8,%9}, {%0,%1,%2,%3};"                   \
        : "+f"((d)[0]), "+f"((d)[1]), "+f"((d)[2]), "+f"((d)[3])                  \
        : "r"((a)[0]), "r"((a)[1]), "r"((a)[2]), "r"((a)[3]), "r"(b0v), "r"(b1v))

// split fp32 -> two fp16 (hi = rn(v), lo = rn(v - hi)); missing part ~2^-22 v
__device__ __forceinline__ void store_split_h(size_t idx, float v) {
    __half h = __float2half_rn(v);
    g_A0[idx] = h;
    g_A1[idx] = __float2half_rn(v - __half2float(h));
}

// =====================================================================
// Kernel 1: path signatures (Chen, depth 3) -> fp16 split into g_A0/g_A1
// =====================================================================
__global__ __launch_bounds__(128) void sig_kernel(
    const float* __restrict__ x,       // (128,512,4)
    const float* __restrict__ W_aug)   // (2,5,4)
{
    const int w  = blockIdx.x;
    const int bg = blockIdx.y;
    const int b  = bg >> 1;
    const int g  = bg & 1;
    const int tid = threadIdx.x;

    __shared__ __align__(16) float xs[32][4];
    __shared__ __align__(16) float dxw[31][10];

    {
        int row = tid >> 2, ch = tid & 3;
        xs[row][ch] = x[(b * STREAM_ + w * STEP_ + row) * INCH + ch];
    }
    __syncthreads();

    for (int idx = tid; idx < 31 * 10; idx += 128) {
        int j = idx / 10, c = idx % 10;
        float v;
        if (c < 4) {
            v = xs[j + 1][c] - xs[j][c];
        } else if (c == 4) {
            v = 1.0f / 511.0f;
        } else {
            int e = c - 5;
            const float* wa = W_aug + (g * EXTRA_ + e) * INCH;
            v = 0.f;
            #pragma unroll
            for (int i = 0; i < 4; i++) v += wa[i] * (xs[j + 1][i] - xs[j][i]);
        }
        dxw[j][c] = v;
    }
    __syncthreads();

    const size_t base = (size_t)(w * B_ + b) * KP2 + (size_t)g * SIGC;

    if (tid < 100) {
        const int a  = tid / 10;
        const int bb = tid % 10;
        float s1a = 0.f, s2 = 0.f;
        float s3[10];
        #pragma unroll
        for (int c = 0; c < 10; c++) s3[c] = 0.f;

        for (int j = 0; j < 31; j++) {
            float dxa = dxw[j][a];
            float dxb = dxw[j][bb];
            float factor = s2 + dxb * (0.5f * s1a + (1.0f / 6.0f) * dxa);
            #pragma unroll
            for (int c = 0; c < 10; c++) s3[c] += factor * dxw[j][c];
            s2  += dxb * (s1a + 0.5f * dxa);
            s1a += dxa;
        }
        if (bb == 0) store_split_h(base + a, s1a);
        store_split_h(base + 10 + tid, s2);
        #pragma unroll
        for (int c = 0; c < 10; c++)
            store_split_h(base + 110 + tid * 10 + c, s3[c]);
    }
    // zero K-pad columns (g==1 block handles it once per row)
    if (g == 1 && tid < (KP2 - F_)) {
        size_t idx = (size_t)(w * B_ + b) * KP2 + F_ + tid;
        g_A0[idx] = __float2half_rn(0.f);
        g_A1[idx] = __float2half_rn(0.f);
    }
}

// =====================================================================
// Kernel 2: round+pad W_ih (768 x 2220) into g_B0 (768 x 2240) fp16
// =====================================================================
__global__ __launch_bounds__(256) void prep_w(const float* __restrict__ Wih)
{
    int idx = blockIdx.x * 256 + threadIdx.x;
    if (idx < NGI * KP2) {
        int n = idx / KP2, k = idx - n * KP2;
        float v = (k < F_) ? Wih[n * F_ + k] : 0.f;
        g_B0[idx] = __float2half_rn(v);
    }
}

// =====================================================================
// Kernel 3: GI = sig @ W_ih^T + b_ih via mma.sync fp16 2-product
// (A0*B0 + A1*B0 = A*B0 exactly; only B-rounding error ~2^-11).
// 64x128 CTA tile (372 tiles, 2 CTAs/SM), 8 warps of 32(M)x32(N),
// K-chunk 64, double-buffered cp.async, SW128 smem, ldmatrix TN.
// =====================================================================
#define A_TILE_B    8192                   // 64 rows x 128 bytes
#define B_TILE_B    16384                  // 128 rows x 128 bytes
#define STAGE_B     (2 * A_TILE_B + B_TILE_B)   // 32768
#define GEMM_SMEM   (2 * STAGE_B)          // 65536 bytes (2 stages)

__global__ __launch_bounds__(256, 2) void gemm_mma(const float* __restrict__ bih)
{
    extern __shared__ char smem[];
    const uint32_t sb = smem_u32(smem);
    const int tid  = threadIdx.x;
    const int lane = tid & 31;
    const int wid  = tid >> 5;
    const int wm   = wid & 1;         // M offset 32*wm
    const int wn   = wid >> 1;        // 0..3 -> N offset 32*wn
    const int m0 = blockIdx.x * 64;
    const int n0 = blockIdx.y * 128;

    const __half* aA0 = g_A0 + (size_t)m0 * KP2;
    const __half* aA1 = g_A1 + (size_t)m0 * KP2;
    const __half* bB0g = g_B0 + (size_t)n0 * KP2;

    auto load_chunk = [&](int c) {
        uint32_t sbase = sb + (uint32_t)(c & 1) * STAGE_B;
        // A0 / A1 : 64 rows x 8 16B-segs = 512 segs each
        #pragma unroll
        for (int tt = 0; tt < 2; tt++) {
            const __half* gp = tt ? aA1 : aA0;
            #pragma unroll
            for (int it = 0; it < 2; it++) {
                int i = tid + it * 256;           // 0..511
                int row = i >> 3, seg = i & 7;
                uint32_t dst = sbase + (uint32_t)tt * A_TILE_B
                             + swz((uint32_t)row * 128 + (uint32_t)seg * 16);
                const void* src = gp + (size_t)row * KP2 + (size_t)c * 64 + seg * 8;
                asm volatile("cp.async.cg.shared.global [%0], [%1], 16;\n"
                             :: "r"(dst), "l"(src));
            }
        }
        // B0 : 128 rows x 8 segs = 1024 segs
        #pragma unroll
        for (int it = 0; it < 4; it++) {
            int i = tid + it * 256;               // 0..1023
            int row = i >> 3, seg = i & 7;
            uint32_t dst = sbase + 2 * A_TILE_B
                         + swz((uint32_t)row * 128 + (uint32_t)seg * 16);
            const void* src = bB0g + (size_t)row * KP2 + (size_t)c * 64 + seg * 8;
            asm volatile("cp.async.cg.shared.global [%0], [%1], 16;\n"
                         :: "r"(dst), "l"(src));
        }
        asm volatile("cp.async.commit_group;\n" ::: "memory");
    };

    float acc[2][4][4];
    #pragma unroll
    for (int i = 0; i < 2; i++)
        #pragma unroll
        for (int jj = 0; jj < 4; jj++)
            #pragma unroll
            for (int k = 0; k < 4; k++) acc[i][jj][k] = 0.f;

    // ldmatrix per-lane address components (same fragment maps, verified R5-R9)
    const uint32_t a_row  = (uint32_t)(wm * 32 + (lane & 15));
    const uint32_t a_byte = (uint32_t)((lane >> 4) << 4);
    const uint32_t b_row  = (uint32_t)(wn * 32 + (lane & 7) + ((lane >> 4) << 3));
    const uint32_t b_byte = (uint32_t)((lane & 8) << 1);

    load_chunk(0);

    for (int c = 0; c < NC; c++) {
        if (c + 1 < NC) load_chunk(c + 1);
        if (c + 1 < NC) asm volatile("cp.async.wait_group 1;\n" ::: "memory");
        else            asm volatile("cp.async.wait_group 0;\n" ::: "memory");
        __syncthreads();

        const uint32_t stage = sb + (uint32_t)(c & 1) * STAGE_B;
        const uint32_t aB0 = stage;
        const uint32_t aB1 = stage + A_TILE_B;
        const uint32_t bB0 = stage + 2 * A_TILE_B;

        #pragma unroll
        for (int ks = 0; ks < 4; ks++) {
            const uint32_t kb = (uint32_t)ks * 32;
            uint32_t a0f[2][4], a1f[2][4];
            #pragma unroll
            for (int mt = 0; mt < 2; mt++) {
                uint32_t off = swz((a_row + mt * 16) * 128 + kb + a_byte);
                LDSM4(a0f[mt][0], a0f[mt][1], a0f[mt][2], a0f[mt][3], aB0 + off);
                LDSM4(a1f[mt][0], a1f[mt][1], a1f[mt][2], a1f[mt][3], aB1 + off);
            }
            uint32_t b0f[2][4];
            #pragma unroll
            for (int nt = 0; nt < 2; nt++) {
                uint32_t off = swz((b_row + nt * 16) * 128 + kb + b_byte);
                LDSM4(b0f[nt][0], b0f[nt][1], b0f[nt][2], b0f[nt][3], bB0 + off);
            }
            #pragma unroll
            for (int mt = 0; mt < 2; mt++) {
                #pragma unroll
                for (int nt = 0; nt < 2; nt++) {
                    MMAH(acc[mt][2 * nt],     a0f[mt], b0f[nt][0], b0f[nt][1]);
                    MMAH(acc[mt][2 * nt + 1], a0f[mt], b0f[nt][2], b0f[nt][3]);
                    MMAH(acc[mt][2 * nt],     a1f[mt], b0f[nt][0], b0f[nt][1]);
                    MMAH(acc[mt][2 * nt + 1], a1f[mt], b0f[nt][2], b0f[nt][3]);
                }
            }
        }
        __syncthreads();
    }

    // epilogue: fragment thread t holds rows {t/4, t/4+8}, cols {2(t%4), +1}
    float2 bias[4];
    {
        const int nbase = n0 + wn * 32 + 2 * (lane & 3);
        #pragma unroll
        for (int nt8 = 0; nt8 < 4; nt8++) {
            bias[nt8].x = bih[nbase + nt8 * 8];
            bias[nt8].y = bih[nbase + nt8 * 8 + 1];
        }
    }
    #pragma unroll
    for (int mt = 0; mt < 2; mt++) {
        const int mlo = m0 + wm * 32 + mt * 16 + (lane >> 2);
        #pragma unroll
        for (int nt8 = 0; nt8 < 4; nt8++) {
            const int n = n0 + wn * 32 + nt8 * 8 + 2 * (lane & 3);
            float2 lo, hi;
            lo.x = acc[mt][nt8][0] + bias[nt8].x;
            lo.y = acc[mt][nt8][1] + bias[nt8].y;
            hi.x = acc[mt][nt8][2] + bias[nt8].x;
            hi.y = acc[mt][nt8][3] + bias[nt8].y;
            *(float2*)(g_gi + (size_t)mlo * NGI + n)       = lo;
            *(float2*)(g_gi + (size_t)(mlo + 8) * NGI + n) = hi;
        }
    }
}

// =====================================================================
// Kernel 4: persistent GRU (R7 shape: 256 thr, W_hh in registers) with
// HIERARCHICAL barriers: 8 independent 16-CTA groups (one per b-tile).
// 128 CTAs = 8 b-tiles(16) x 16 j-tiles(16).
// Lane (warp w, jj=lane>>4, kc=lane&15) owns j = j0+2w+jj, k-slice
// kc*16..+15: W_hh[3][16] in 48 registers for all 31 steps.
// =====================================================================
#define GRU_CTAS   128

__global__ __launch_bounds__(256, 1) void gru_persist(
    const float* __restrict__ Whh,   // (768,256)
    const float* __restrict__ bhh,   // (768)
    const float* __restrict__ Wout,  // (10,256)
    const float* __restrict__ bout,  // (10)
    float* __restrict__ out)         // (128,10)
{
    // hs[b][i4][kc][4] : element k of row b at ((b*4 + (k>>2)&3)*16 + k>>4)*4 + (k&3)
    __shared__ __align__(16) float hs[4096];   // 16 KB

    const int tid  = threadIdx.x;
    const int w    = tid >> 5;
    const int lane = tid & 31;
    const int jj   = lane >> 4;
    const int kc   = lane & 15;
    const int bt = blockIdx.x >> 4, jt = blockIdx.x & 15;
    const int b0 = bt * 16, j0 = jt * 16;
    const int j  = j0 + (w << 1) + jj;   // this lane's gate column
    const int b  = b0 + kc;              // this lane's output batch row

    // ---- one-time: W_hh[3 gates][my 16-k slice] -> registers ----
    float4 W4[3][4];
    #pragma unroll
    for (int g = 0; g < 3; g++)
        #pragma unroll
        for (int i4 = 0; i4 < 4; i4++)
            W4[g][i4] = *(const float4*)&Whh[(g * RNN_ + j) * RNN_ + kc * 16 + i4 * 4];

    const float br = bhh[j], bz = bhh[RNN_ + j], bn = bhh[2 * RNN_ + j];
    // h_prev smem index for (b=kc row, col j)
    const int hprev_idx = ((kc * 4 + ((j >> 2) & 3)) * 16 + (j >> 4)) * 4 + (j & 3);

    for (int t = 0; t < W_; t++) {
        // ---- fill hs (swizzled) ----
        if (t == 0) {
            #pragma unroll
            for (int i = tid; i < 1024; i += 256)
                *(float4*)&hs[i * 4] = make_float4(0.f, 0.f, 0.f, 0.f);
        } else {
            const float* hi = g_h[t & 1];
            #pragma unroll
            for (int i = tid; i < 1024; i += 256) {
                int bb = i >> 6, q = i & 63;         // q = k/4
                int kcs = q >> 2, i4 = q & 3;
                float4 v = __ldcg((const float4*)&hi[(b0 + bb) * RNN_ + q * 4]);
                *(float4*)&hs[((bb * 4 + i4) * 16 + kcs) * 4] = v;
            }
        }
        __syncthreads();

        // prefetch gi for this lane's output (consumed after reduction)
        const float* gi_t = g_gi + (size_t)t * (B_ * NGI) + (size_t)b * NGI;
        float ir  = __ldcg(&gi_t[j]);
        float iz  = __ldcg(&gi_t[RNN_ + j]);
        float inn = __ldcg(&gi_t[2 * RNN_ + j]);

        // ---- partials: all 16 b-rows over my 16-k slice ----
        float acc[16][3];
        #pragma unroll
        for (int bb = 0; bb < 16; bb++) {
            float4 h0 = *(const float4*)&hs[((bb * 4 + 0) * 16 + kc) * 4];
            float4 h1 = *(const float4*)&hs[((bb * 4 + 1) * 16 + kc) * 4];
            float4 h2 = *(const float4*)&hs[((bb * 4 + 2) * 16 + kc) * 4];
            float4 h3 = *(const float4*)&hs[((bb * 4 + 3) * 16 + kc) * 4];
            #pragma unroll
            for (int g = 0; g < 3; g++) {
                float s;
                s  = W4[g][0].x * h0.x + W4[g][0].y * h0.y + W4[g][0].z * h0.z + W4[g][0].w * h0.w;
                s += W4[g][1].x * h1.x + W4[g][1].y * h1.y + W4[g][1].z * h1.z + W4[g][1].w * h1.w;
                s += W4[g][2].x * h2.x + W4[g][2].y * h2.y + W4[g][2].z * h2.z + W4[g][2].w * h2.w;
                s += W4[g][3].x * h3.x + W4[g][3].y * h3.y + W4[g][3].z * h3.z + W4[g][3].w * h3.w;
                acc[bb][g] = s;
            }
        }

        // ---- transpose-butterfly reduce over 16 kc-lanes (45 SHFL) ----
        #pragma unroll
        for (int m = 8; m >= 1; m >>= 1) {
            #pragma unroll
            for (int bb = 0; bb < m; bb++) {
                #pragma unroll
                for (int g = 0; g < 3; g++) {
                    float lo = acc[bb][g], hi2 = acc[bb + m][g];
                    float send = (kc & m) ? lo  : hi2;
                    float keep = (kc & m) ? hi2 : lo;
                    acc[bb][g] = keep + __shfl_xor_sync(0xffffffffu, send, m);
                }
            }
        }

        // ---- gates for (b, j) ----
        float r = 1.f / (1.f + expf(-(ir + acc[0][0] + br)));
        float z = 1.f / (1.f + expf(-(iz + acc[0][1] + bz)));
        float n = tanhf(inn + r * (acc[0][2] + bn));
        float hprev = hs[hprev_idx];
        g_h[(t + 1) & 1][b * RNN_ + j] = (1.f - z) * n + z * hprev;

        // ---- hierarchical barrier: only the 16 CTAs sharing bt ----
        __threadfence();
        __syncthreads();
        if (tid == 0) {
            unsigned gen = g_bars[bt].gen;
            if (atomicAdd(&g_bars[bt].cnt, 1u) == 15u) {
                g_bars[bt].cnt = 0;
                __threadfence();
                g_bars[bt].gen = gen + 1;
            } else {
                while (g_bars[bt].gen == gen) __nanosleep(16);
            }
        }
        __syncthreads();
    }

    // ---- output head: 8 CTAs (jt==0), 16 b-rows x 10 outputs each ----
    if (jt == 0) {
        const float* hf = g_h[W_ & 1];   // final h after 31 steps
        for (int i = tid; i < 16 * OUT_; i += 256) {
            int bb = b0 + i / OUT_, o = i % OUT_;
            float s = 0.f;
            #pragma unroll 8
            for (int k = 0; k < RNN_; k += 4) {
                float4 h4 = __ldcg((const float4*)&hf[bb * RNN_ + k]);
                float4 w4 = *(const float4*)&Wout[o * RNN_ + k];
                s += h4.x * w4.x + h4.y * w4.y + h4.z * w4.z + h4.w * w4.w;
            }
            out[bb * OUT_ + o] = 1.f / (1.f + expf(-(s + bout[o])));
        }
    }
}

// =====================================================================
extern "C" void kernel_launch(void* const* d_in, const int* in_sizes, int n_in,
                              void* d_out, int out_size)
{
    const float* x     = (const float*)d_in[0];
    const float* W_aug = (const float*)d_in[1];
    // d_in[2] = b_aug: constant, cancels in increments
    const float* W_ih  = (const float*)d_in[3];
    const float* W_hh  = (const float*)d_in[4];
    const float* b_ih  = (const float*)d_in[5];
    const float* b_hh  = (const float*)d_in[6];
    const float* W_out = (const float*)d_in[7];
    const float* b_out = (const float*)d_in[8];
    float* out = (float*)d_out;

    cudaFuncSetAttribute(gemm_mma, cudaFuncAttributeMaxDynamicSharedMemorySize, GEMM_SMEM);

    sig_kernel<<<dim3(W_, B_ * G_), 128>>>(x, W_aug);
    prep_w<<<(NGI * KP2 + 255) / 256, 256>>>(W_ih);
    gemm_mma<<<dim3(MROWS / 64, NGI / 128), 256, GEMM_SMEM>>>(b_ih);
    gru_persist<<<GRU_CTAS, 256>>>(W_hh, b_hh, W_out, b_out, out);
}

// round 11
// speedup vs baseline: 1.1515x; 1.0041x over previous
#include <cuda_runtime.h>
#include <cuda_fp16.h>
#include <math.h>
#include <stdint.h>

// ---------------- problem constants ----------------
#define B_      128
#define STREAM_ 512
#define INCH    4
#define EXTRA_  5
#define G_      2
#define STEP_   16
#define SIGC    1110        // C + C^2 + C^3, C=10
#define W_      31          // windows
#define F_      2220        // GROUPS * SIGC
#define RNN_    256
#define OUT_    10
#define KP2     2240        // F_ padded to multiple of 64 (fp16 chunk)
#define MROWS   (W_ * B_)   // 3968
#define NGI     768         // 3 * RNN
#define NC      (KP2 / 64)  // 35 K-chunks of 64 fp16 (128 bytes)

// ---------------- device scratch (static, allowed) ----------------
__device__ __half g_A0[MROWS * KP2];          // sig hi fp16 (~17.8 MB)
__device__ __half g_A1[MROWS * KP2];          // sig lo fp16
__device__ __half g_B0[NGI * KP2];            // W_ih fp16  (~3.4 MB)
__device__ float g_gi[W_ * NGI * B_];         // TRANSPOSED: [t][gate][batch]
__device__ float g_h [2][B_ * RNN_];          // ping-pong hidden state

// global grid barrier (gen monotonic across graph replays)
__device__ volatile unsigned g_bar_gen;
__device__ unsigned g_bar_cnt;

// ---------------- PTX helpers (portable: sm_80/90 class only) ----------------
__device__ __forceinline__ uint32_t smem_u32(const void* p) {
    uint32_t a;
    asm("{ .reg .u64 t; cvta.to.shared.u64 t, %1; cvt.u32.u64 %0, t; }" : "=r"(a) : "l"(p));
    return a;
}

__device__ __forceinline__ uint32_t swz(uint32_t off) { return off ^ ((off >> 3) & 0x70); }

#define LDSM4(r0, r1, r2, r3, addr)                                               \
    asm volatile("ldmatrix.sync.aligned.m8n8.x4.shared.b16 {%0,%1,%2,%3}, [%4];"  \
        : "=r"(r0), "=r"(r1), "=r"(r2), "=r"(r3) : "r"(addr))

// D += A(16x16) * B(16x8), fp16 in, fp32 accum. row.col = both K-contiguous.
#define MMAH(d, a, b0v, b1v)                                                      \
    asm volatile("mma.sync.aligned.m16n8k16.row.col.f32.f16.f16.f32 "             \
        "{%0,%1,%2,%3}, {%4,%5,%6,%7}, {%8,%9}, {%0,%1,%2,%3};"                   \
        : "+f"((d)[0]), "+f"((d)[1]), "+f"((d)[2]), "+f"((d)[3])                  \
        : "r"((a)[0]), "r"((a)[1]), "r"((a)[2]), "r"((a)[3]), "r"(b0v), "r"(b1v))

// split fp32 -> two fp16 (hi = rn(v), lo = rn(v - hi)); missing part ~2^-22 v
__device__ __forceinline__ void store_split_h(size_t idx, float v) {
    __half h = __float2half_rn(v);
    g_A0[idx] = h;
    g_A1[idx] = __float2half_rn(v - __half2float(h));
}

// =====================================================================
// Kernel 1: path signatures (Chen, depth 3) -> fp16 split into g_A0/g_A1
// =====================================================================
__global__ __launch_bounds__(128) void sig_kernel(
    const float* __restrict__ x,       // (128,512,4)
    const float* __restrict__ W_aug)   // (2,5,4)
{
    const int w  = blockIdx.x;
    const int bg = blockIdx.y;
    const int b  = bg >> 1;
    const int g  = bg & 1;
    const int tid = threadIdx.x;

    __shared__ __align__(16) float xs[32][4];
    __shared__ __align__(16) float dxw[31][10];

    {
        int row = tid >> 2, ch = tid & 3;
        xs[row][ch] = x[(b * STREAM_ + w * STEP_ + row) * INCH + ch];
    }
    __syncthreads();

    for (int idx = tid; idx < 31 * 10; idx += 128) {
        int j = idx / 10, c = idx % 10;
        float v;
        if (c < 4) {
            v = xs[j + 1][c] - xs[j][c];
        } else if (c == 4) {
            v = 1.0f / 511.0f;
        } else {
            int e = c - 5;
            const float* wa = W_aug + (g * EXTRA_ + e) * INCH;
            v = 0.f;
            #pragma unroll
            for (int i = 0; i < 4; i++) v += wa[i] * (xs[j + 1][i] - xs[j][i]);
        }
        dxw[j][c] = v;
    }
    __syncthreads();

    const size_t base = (size_t)(w * B_ + b) * KP2 + (size_t)g * SIGC;

    if (tid < 100) {
        const int a  = tid / 10;
        const int bb = tid % 10;
        float s1a = 0.f, s2 = 0.f;
        float s3[10];
        #pragma unroll
        for (int c = 0; c < 10; c++) s3[c] = 0.f;

        for (int j = 0; j < 31; j++) {
            float dxa = dxw[j][a];
            float dxb = dxw[j][bb];
            float factor = s2 + dxb * (0.5f * s1a + (1.0f / 6.0f) * dxa);
            #pragma unroll
            for (int c = 0; c < 10; c++) s3[c] += factor * dxw[j][c];
            s2  += dxb * (s1a + 0.5f * dxa);
            s1a += dxa;
        }
        if (bb == 0) store_split_h(base + a, s1a);
        store_split_h(base + 10 + tid, s2);
        #pragma unroll
        for (int c = 0; c < 10; c++)
            store_split_h(base + 110 + tid * 10 + c, s3[c]);
    }
    // zero K-pad columns (g==1 block handles it once per row)
    if (g == 1 && tid < (KP2 - F_)) {
        size_t idx = (size_t)(w * B_ + b) * KP2 + F_ + tid;
        g_A0[idx] = __float2half_rn(0.f);
        g_A1[idx] = __float2half_rn(0.f);
    }
}

// =====================================================================
// Kernel 2: round+pad W_ih (768 x 2220) into g_B0 (768 x 2240) fp16
// =====================================================================
__global__ __launch_bounds__(256) void prep_w(const float* __restrict__ Wih)
{
    int idx = blockIdx.x * 256 + threadIdx.x;
    if (idx < NGI * KP2) {
        int n = idx / KP2, k = idx - n * KP2;
        float v = (k < F_) ? Wih[n * F_ + k] : 0.f;
        g_B0[idx] = __float2half_rn(v);
    }
}

// =====================================================================
// Kernel 3: GI = sig @ W_ih^T + b_ih via mma.sync fp16 2-product.
// 64x64 CTA tile (grid 62x12 = 744 CTAs, 2/SM — makespan 3 half-tiles
// vs 2 full tiles before). 8 warps of 32(M)x16(N). Epilogue writes
// TRANSPOSED gi [t][gate][batch] for coalesced GRU reads.
// =====================================================================
#define T64_B       8192                   // 64 rows x 128 bytes
#define STAGE_B     (3 * T64_B)            // A0,A1,B tiles = 24576
#define GEMM_SMEM   (2 * STAGE_B)          // 49152 bytes (2 stages)

__global__ __launch_bounds__(256, 2) void gemm_mma(const float* __restrict__ bih)
{
    extern __shared__ char smem[];
    const uint32_t sb = smem_u32(smem);
    const int tid  = threadIdx.x;
    const int lane = tid & 31;
    const int wid  = tid >> 5;
    const int wm   = wid & 1;         // M offset 32*wm
    const int wn   = wid >> 1;        // 0..3 -> N offset 16*wn
    const int m0 = blockIdx.x * 64;
    const int n0 = blockIdx.y * 64;

    const __half* aA0 = g_A0 + (size_t)m0 * KP2;
    const __half* aA1 = g_A1 + (size_t)m0 * KP2;
    const __half* bB0g = g_B0 + (size_t)n0 * KP2;

    auto load_chunk = [&](int c) {
        uint32_t sbase = sb + (uint32_t)(c & 1) * STAGE_B;
        // A0 / A1 / B : each 64 rows x 8 16B-segs = 512 segs
        #pragma unroll
        for (int tt = 0; tt < 3; tt++) {
            const __half* gp = (tt == 0) ? aA0 : (tt == 1) ? aA1 : bB0g;
            #pragma unroll
            for (int it = 0; it < 2; it++) {
                int i = tid + it * 256;           // 0..511
                int row = i >> 3, seg = i & 7;
                uint32_t dst = sbase + (uint32_t)tt * T64_B
                             + swz((uint32_t)row * 128 + (uint32_t)seg * 16);
                const void* src = gp + (size_t)row * KP2 + (size_t)c * 64 + seg * 8;
                asm volatile("cp.async.cg.shared.global [%0], [%1], 16;\n"
                             :: "r"(dst), "l"(src));
            }
        }
        asm volatile("cp.async.commit_group;\n" ::: "memory");
    };

    float acc[2][2][4];
    #pragma unroll
    for (int i = 0; i < 2; i++)
        #pragma unroll
        for (int jj = 0; jj < 2; jj++)
            #pragma unroll
            for (int k = 0; k < 4; k++) acc[i][jj][k] = 0.f;

    // ldmatrix per-lane address components (fragment maps verified R5-R10)
    const uint32_t a_row  = (uint32_t)(wm * 32 + (lane & 15));
    const uint32_t a_byte = (uint32_t)((lane >> 4) << 4);
    const uint32_t b_row  = (uint32_t)(wn * 16 + (lane & 7) + ((lane >> 4) << 3));
    const uint32_t b_byte = (uint32_t)((lane & 8) << 1);

    load_chunk(0);

    for (int c = 0; c < NC; c++) {
        if (c + 1 < NC) load_chunk(c + 1);
        if (c + 1 < NC) asm volatile("cp.async.wait_group 1;\n" ::: "memory");
        else            asm volatile("cp.async.wait_group 0;\n" ::: "memory");
        __syncthreads();

        const uint32_t stage = sb + (uint32_t)(c & 1) * STAGE_B;
        const uint32_t aB0 = stage;
        const uint32_t aB1 = stage + T64_B;
        const uint32_t bB0 = stage + 2 * T64_B;

        #pragma unroll
        for (int ks = 0; ks < 4; ks++) {
            const uint32_t kb = (uint32_t)ks * 32;
            uint32_t a0f[2][4], a1f[2][4];
            #pragma unroll
            for (int mt = 0; mt < 2; mt++) {
                uint32_t off = swz((a_row + mt * 16) * 128 + kb + a_byte);
                LDSM4(a0f[mt][0], a0f[mt][1], a0f[mt][2], a0f[mt][3], aB0 + off);
                LDSM4(a1f[mt][0], a1f[mt][1], a1f[mt][2], a1f[mt][3], aB1 + off);
            }
            uint32_t bf[4];   // covers warp's 16 N x 16 k
            {
                uint32_t off = swz(b_row * 128 + kb + b_byte);
                LDSM4(bf[0], bf[1], bf[2], bf[3], bB0 + off);
            }
            #pragma unroll
            for (int mt = 0; mt < 2; mt++) {
                MMAH(acc[mt][0], a0f[mt], bf[0], bf[1]);
                MMAH(acc[mt][1], a0f[mt], bf[2], bf[3]);
                MMAH(acc[mt][0], a1f[mt], bf[0], bf[1]);
                MMAH(acc[mt][1], a1f[mt], bf[2], bf[3]);
            }
        }
        __syncthreads();
    }

    // epilogue: transpose-store into g_gi[t][n][b].
    // fragment thread holds rows {mlo, mlo+8}, cols {n, n+1}.
    const int t     = m0 >> 7;                 // tile lies in one t (m0 mult of 64)
    const int bbase = (m0 & 127) + wm * 32 + (lane >> 2);
    float* gT = g_gi + (size_t)t * NGI * B_;
    float2 bias[2];
    {
        const int nb = n0 + wn * 16 + 2 * (lane & 3);
        bias[0].x = bih[nb];     bias[0].y = bih[nb + 1];
        bias[1].x = bih[nb + 8]; bias[1].y = bih[nb + 9];
    }
    #pragma unroll
    for (int mt = 0; mt < 2; mt++) {
        const int blo = bbase + mt * 16;
        #pragma unroll
        for (int nt8 = 0; nt8 < 2; nt8++) {
            const int n = n0 + wn * 16 + nt8 * 8 + 2 * (lane & 3);
            gT[(size_t)n * B_ + blo]           = acc[mt][nt8][0] + bias[nt8].x;
            gT[(size_t)(n + 1) * B_ + blo]     = acc[mt][nt8][1] + bias[nt8].y;
            gT[(size_t)n * B_ + blo + 8]       = acc[mt][nt8][2] + bias[nt8].x;
            gT[(size_t)(n + 1) * B_ + blo + 8] = acc[mt][nt8][3] + bias[nt8].y;
        }
    }
}

// =====================================================================
// Kernel 4: persistent GRU (R7 shape: 256 thr, W_hh in registers,
// GLOBAL barrier — empirically fastest). 128 CTAs = 8 bt x 16 jt.
// Lane (warp w, jj=lane>>4, kc=lane&15) owns j = j0+2w+jj, k-slice
// kc*16..+15: W_hh[3][16] in 48 registers for all 31 steps.
// gi reads now COALESCED via transposed layout [t][gate][batch].
// =====================================================================
#define GRU_CTAS   128

__global__ __launch_bounds__(256, 1) void gru_persist(
    const float* __restrict__ Whh,   // (768,256)
    const float* __restrict__ bhh,   // (768)
    const float* __restrict__ Wout,  // (10,256)
    const float* __restrict__ bout,  // (10)
    float* __restrict__ out)         // (128,10)
{
    // hs[b][i4][kc][4] : element k of row b at ((b*4 + (k>>2)&3)*16 + k>>4)*4 + (k&3)
    __shared__ __align__(16) float hs[4096];   // 16 KB

    const int tid  = threadIdx.x;
    const int w    = tid >> 5;
    const int lane = tid & 31;
    const int jj   = lane >> 4;
    const int kc   = lane & 15;
    const int bt = blockIdx.x >> 4, jt = blockIdx.x & 15;
    const int b0 = bt * 16, j0 = jt * 16;
    const int j  = j0 + (w << 1) + jj;   // this lane's gate column
    const int b  = b0 + kc;              // this lane's output batch row

    // ---- one-time: W_hh[3 gates][my 16-k slice] -> registers ----
    float4 W4[3][4];
    #pragma unroll
    for (int g = 0; g < 3; g++)
        #pragma unroll
        for (int i4 = 0; i4 < 4; i4++)
            W4[g][i4] = *(const float4*)&Whh[(g * RNN_ + j) * RNN_ + kc * 16 + i4 * 4];

    const float br = bhh[j], bz = bhh[RNN_ + j], bn = bhh[2 * RNN_ + j];
    // h_prev smem index for (b=kc row, col j)
    const int hprev_idx = ((kc * 4 + ((j >> 2) & 3)) * 16 + (j >> 4)) * 4 + (j & 3);

    for (int t = 0; t < W_; t++) {
        // ---- fill hs (swizzled) ----
        if (t == 0) {
            #pragma unroll
            for (int i = tid; i < 1024; i += 256)
                *(float4*)&hs[i * 4] = make_float4(0.f, 0.f, 0.f, 0.f);
        } else {
            const float* hi = g_h[t & 1];
            #pragma unroll
            for (int i = tid; i < 1024; i += 256) {
                int bb = i >> 6, q = i & 63;         // q = k/4
                int kcs = q >> 2, i4 = q & 3;
                float4 v = __ldcg((const float4*)&hi[(b0 + bb) * RNN_ + q * 4]);
                *(float4*)&hs[((bb * 4 + i4) * 16 + kcs) * 4] = v;
            }
        }
        __syncthreads();

        // prefetch gi (transposed layout: lanes kc=0..15 -> consecutive b)
        const float* giT = g_gi + (size_t)t * NGI * B_;
        float ir  = __ldcg(&giT[(size_t)j * B_ + b]);
        float iz  = __ldcg(&giT[(size_t)(RNN_ + j) * B_ + b]);
        float inn = __ldcg(&giT[(size_t)(2 * RNN_ + j) * B_ + b]);

        // ---- partials: all 16 b-rows over my 16-k slice ----
        float acc[16][3];
        #pragma unroll
        for (int bb = 0; bb < 16; bb++) {
            float4 h0 = *(const float4*)&hs[((bb * 4 + 0) * 16 + kc) * 4];
            float4 h1 = *(const float4*)&hs[((bb * 4 + 1) * 16 + kc) * 4];
            float4 h2 = *(const float4*)&hs[((bb * 4 + 2) * 16 + kc) * 4];
            float4 h3 = *(const float4*)&hs[((bb * 4 + 3) * 16 + kc) * 4];
            #pragma unroll
            for (int g = 0; g < 3; g++) {
                float s;
                s  = W4[g][0].x * h0.x + W4[g][0].y * h0.y + W4[g][0].z * h0.z + W4[g][0].w * h0.w;
                s += W4[g][1].x * h1.x + W4[g][1].y * h1.y + W4[g][1].z * h1.z + W4[g][1].w * h1.w;
                s += W4[g][2].x * h2.x + W4[g][2].y * h2.y + W4[g][2].z * h2.z + W4[g][2].w * h2.w;
                s += W4[g][3].x * h3.x + W4[g][3].y * h3.y + W4[g][3].z * h3.z + W4[g][3].w * h3.w;
                acc[bb][g] = s;
            }
        }

        // ---- transpose-butterfly reduce over 16 kc-lanes (45 SHFL) ----
        #pragma unroll
        for (int m = 8; m >= 1; m >>= 1) {
            #pragma unroll
            for (int bb = 0; bb < m; bb++) {
                #pragma unroll
                for (int g = 0; g < 3; g++) {
                    float lo = acc[bb][g], hi2 = acc[bb + m][g];
                    float send = (kc & m) ? lo  : hi2;
                    float keep = (kc & m) ? hi2 : lo;
                    acc[bb][g] = keep + __shfl_xor_sync(0xffffffffu, send, m);
                }
            }
        }

        // ---- gates for (b, j) ----
        float r = 1.f / (1.f + expf(-(ir + acc[0][0] + br)));
        float z = 1.f / (1.f + expf(-(iz + acc[0][1] + bz)));
        float n = tanhf(inn + r * (acc[0][2] + bn));
        float hprev = hs[hprev_idx];
        g_h[(t + 1) & 1][b * RNN_ + j] = (1.f - z) * n + z * hprev;

        // ---- global grid barrier (empirically fastest variant) ----
        __threadfence();
        __syncthreads();
        if (tid == 0) {
            unsigned gen = g_bar_gen;
            if (atomicAdd(&g_bar_cnt, 1u) == GRU_CTAS - 1) {
                g_bar_cnt = 0;
                __threadfence();
                g_bar_gen = gen + 1;
            } else {
                while (g_bar_gen == gen) __nanosleep(32);
            }
        }
        __syncthreads();
    }

    // ---- output head: 8 CTAs (jt==0), 16 b-rows x 10 outputs each ----
    if (jt == 0) {
        const float* hf = g_h[W_ & 1];   // final h after 31 steps
        for (int i = tid; i < 16 * OUT_; i += 256) {
            int bb = b0 + i / OUT_, o = i % OUT_;
            float s = 0.f;
            #pragma unroll 8
            for (int k = 0; k < RNN_; k += 4) {
                float4 h4 = __ldcg((const float4*)&hf[bb * RNN_ + k]);
                float4 w4 = *(const float4*)&Wout[o * RNN_ + k];
                s += h4.x * w4.x + h4.y * w4.y + h4.z * w4.z + h4.w * w4.w;
            }
            out[bb * OUT_ + o] = 1.f / (1.f + expf(-(s + bout[o])));
        }
    }
}

// =====================================================================
extern "C" void kernel_launch(void* const* d_in, const int* in_sizes, int n_in,
                              void* d_out, int out_size)
{
    const float* x     = (const float*)d_in[0];
    const float* W_aug = (const float*)d_in[1];
    // d_in[2] = b_aug: constant, cancels in increments
    const float* W_ih  = (const float*)d_in[3];
    const float* W_hh  = (const float*)d_in[4];
    const float* b_ih  = (const float*)d_in[5];
    const float* b_hh  = (const float*)d_in[6];
    const float* W_out = (const float*)d_in[7];
    const float* b_out = (const float*)d_in[8];
    float* out = (float*)d_out;

    cudaFuncSetAttribute(gemm_mma, cudaFuncAttributeMaxDynamicSharedMemorySize, GEMM_SMEM);

    sig_kernel<<<dim3(W_, B_ * G_), 128>>>(x, W_aug);
    prep_w<<<(NGI * KP2 + 255) / 256, 256>>>(W_ih);
    gemm_mma<<<dim3(MROWS / 64, NGI / 64), 256, GEMM_SMEM>>>(b_ih);
    gru_persist<<<GRU_CTAS, 256>>>(W_hh, b_hh, W_out, b_out, out);
}

// round 12
// speedup vs baseline: 1.4076x; 1.2224x over previous
#include <cuda_runtime.h>
#include <cuda_fp16.h>
#include <math.h>
#include <stdint.h>

// ---------------- problem constants ----------------
#define B_      128
#define STREAM_ 512
#define INCH    4
#define EXTRA_  5
#define G_      2
#define STEP_   16
#define SIGC    1110        // C + C^2 + C^3, C=10
#define W_      31          // windows
#define F_      2220        // GROUPS * SIGC
#define RNN_    256
#define OUT_    10
#define KP2     2240        // F_ padded to multiple of 64 (fp16 chunk)
#define MROWS   (W_ * B_)   // 3968
#define NGI     768         // 3 * RNN
#define NC      (KP2 / 64)  // 35 K-chunks of 64 fp16 (128 bytes)

// ---------------- device scratch (static, allowed) ----------------
__device__ __half g_A0[MROWS * KP2];          // sig fp16 (~17.8 MB)
__device__ __half g_B0[NGI * KP2];            // W_ih fp16 (~3.4 MB)
__device__ float g_gi[MROWS * NGI];           // [t][b][gate] (~12 MB)
__device__ float g_h [2][B_ * RNN_];          // ping-pong hidden state

// global grid barrier (gen monotonic across graph replays)
__device__ volatile unsigned g_bar_gen;
__device__ unsigned g_bar_cnt;

// ---------------- PTX helpers (portable: sm_80/90 class only) ----------------
__device__ __forceinline__ uint32_t smem_u32(const void* p) {
    uint32_t a;
    asm("{ .reg .u64 t; cvta.to.shared.u64 t, %1; cvt.u32.u64 %0, t; }" : "=r"(a) : "l"(p));
    return a;
}

__device__ __forceinline__ uint32_t swz(uint32_t off) { return off ^ ((off >> 3) & 0x70); }

#define LDSM4(r0, r1, r2, r3, addr)                                               \
    asm volatile("ldmatrix.sync.aligned.m8n8.x4.shared.b16 {%0,%1,%2,%3}, [%4];"  \
        : "=r"(r0), "=r"(r1), "=r"(r2), "=r"(r3) : "r"(addr))

// D += A(16x16) * B(16x8), fp16 in, fp32 accum. row.col = both K-contiguous.
#define MMAH(d, a, b0v, b1v)                                                      \
    asm volatile("mma.sync.aligned.m16n8k16.row.col.f32.f16.f16.f32 "             \
        "{%0,%1,%2,%3}, {%4,%5,%6,%7}, {%8,%9}, {%0,%1,%2,%3};"                   \
        : "+f"((d)[0]), "+f"((d)[1]), "+f"((d)[2]), "+f"((d)[3])                  \
        : "r"((a)[0]), "r"((a)[1]), "r"((a)[2]), "r"((a)[3]), "r"(b0v), "r"(b1v))

// =====================================================================
// Kernel 1: path signatures (Chen, depth 3) -> fp16 (single-rounded)
// =====================================================================
__global__ __launch_bounds__(128) void sig_kernel(
    const float* __restrict__ x,       // (128,512,4)
    const float* __restrict__ W_aug)   // (2,5,4)
{
    const int w  = blockIdx.x;
    const int bg = blockIdx.y;
    const int b  = bg >> 1;
    const int g  = bg & 1;
    const int tid = threadIdx.x;

    __shared__ __align__(16) float xs[32][4];
    __shared__ __align__(16) float dxw[31][10];

    {
        int row = tid >> 2, ch = tid & 3;
        xs[row][ch] = x[(b * STREAM_ + w * STEP_ + row) * INCH + ch];
    }
    __syncthreads();

    for (int idx = tid; idx < 31 * 10; idx += 128) {
        int j = idx / 10, c = idx % 10;
        float v;
        if (c < 4) {
            v = xs[j + 1][c] - xs[j][c];
        } else if (c == 4) {
            v = 1.0f / 511.0f;
        } else {
            int e = c - 5;
            const float* wa = W_aug + (g * EXTRA_ + e) * INCH;
            v = 0.f;
            #pragma unroll
            for (int i = 0; i < 4; i++) v += wa[i] * (xs[j + 1][i] - xs[j][i]);
        }
        dxw[j][c] = v;
    }
    __syncthreads();

    const size_t base = (size_t)(w * B_ + b) * KP2 + (size_t)g * SIGC;

    if (tid < 100) {
        const int a  = tid / 10;
        const int bb = tid % 10;
        float s1a = 0.f, s2 = 0.f;
        float s3[10];
        #pragma unroll
        for (int c = 0; c < 10; c++) s3[c] = 0.f;

        for (int j = 0; j < 31; j++) {
            float dxa = dxw[j][a];
            float dxb = dxw[j][bb];
            float factor = s2 + dxb * (0.5f * s1a + (1.0f / 6.0f) * dxa);
            #pragma unroll
            for (int c = 0; c < 10; c++) s3[c] += factor * dxw[j][c];
            s2  += dxb * (s1a + 0.5f * dxa);
            s1a += dxa;
        }
        if (bb == 0) g_A0[base + a] = __float2half_rn(s1a);
        g_A0[base + 10 + tid] = __float2half_rn(s2);
        #pragma unroll
        for (int c = 0; c < 10; c++)
            g_A0[base + 110 + tid * 10 + c] = __float2half_rn(s3[c]);
    }
    // zero K-pad columns (g==1 block handles it once per row)
    if (g == 1 && tid < (KP2 - F_))
        g_A0[(size_t)(w * B_ + b) * KP2 + F_ + tid] = __float2half_rn(0.f);
}

// =====================================================================
// Kernel 2: round+pad W_ih (768 x 2220) into g_B0 (768 x 2240) fp16
// =====================================================================
__global__ __launch_bounds__(256) void prep_w(const float* __restrict__ Wih)
{
    int idx = blockIdx.x * 256 + threadIdx.x;
    if (idx < NGI * KP2) {
        int n = idx / KP2, k = idx - n * KP2;
        float v = (k < F_) ? Wih[n * F_ + k] : 0.f;
        g_B0[idx] = __float2half_rn(v);
    }
}

// =====================================================================
// Kernel 3: GI = sig @ W_ih^T + b_ih, SINGLE-product fp16 mma.sync.
// 64x128 CTA tile (372 CTAs, 2/SM), 8 warps of 32(M)x32(N),
// K-chunk 64, double-buffered cp.async, SW128 smem, ldmatrix TN.
// MMA floor halves vs 2-product: ~51 us.
// =====================================================================
#define A_TILE_B    8192                   // 64 rows x 128 bytes
#define B_TILE_B    16384                  // 128 rows x 128 bytes
#define STAGE_B     (A_TILE_B + B_TILE_B)  // 24576
#define GEMM_SMEM   (2 * STAGE_B)          // 49152 bytes (2 stages)

__global__ __launch_bounds__(256, 2) void gemm_mma(const float* __restrict__ bih)
{
    extern __shared__ char smem[];
    const uint32_t sb = smem_u32(smem);
    const int tid  = threadIdx.x;
    const int lane = tid & 31;
    const int wid  = tid >> 5;
    const int wm   = wid & 1;         // M offset 32*wm
    const int wn   = wid >> 1;        // 0..3 -> N offset 32*wn
    const int m0 = blockIdx.x * 64;
    const int n0 = blockIdx.y * 128;

    const __half* aA0  = g_A0 + (size_t)m0 * KP2;
    const __half* bB0g = g_B0 + (size_t)n0 * KP2;

    auto load_chunk = [&](int c) {
        uint32_t sbase = sb + (uint32_t)(c & 1) * STAGE_B;
        // A : 64 rows x 8 16B-segs = 512 segs
        #pragma unroll
        for (int it = 0; it < 2; it++) {
            int i = tid + it * 256;               // 0..511
            int row = i >> 3, seg = i & 7;
            uint32_t dst = sbase + swz((uint32_t)row * 128 + (uint32_t)seg * 16);
            const void* src = aA0 + (size_t)row * KP2 + (size_t)c * 64 + seg * 8;
            asm volatile("cp.async.cg.shared.global [%0], [%1], 16;\n"
                         :: "r"(dst), "l"(src));
        }
        // B : 128 rows x 8 segs = 1024 segs
        #pragma unroll
        for (int it = 0; it < 4; it++) {
            int i = tid + it * 256;               // 0..1023
            int row = i >> 3, seg = i & 7;
            uint32_t dst = sbase + A_TILE_B
                         + swz((uint32_t)row * 128 + (uint32_t)seg * 16);
            const void* src = bB0g + (size_t)row * KP2 + (size_t)c * 64 + seg * 8;
            asm volatile("cp.async.cg.shared.global [%0], [%1], 16;\n"
                         :: "r"(dst), "l"(src));
        }
        asm volatile("cp.async.commit_group;\n" ::: "memory");
    };

    float acc[2][4][4];
    #pragma unroll
    for (int i = 0; i < 2; i++)
        #pragma unroll
        for (int jj = 0; jj < 4; jj++)
            #pragma unroll
            for (int k = 0; k < 4; k++) acc[i][jj][k] = 0.f;

    // ldmatrix per-lane address components (fragment maps validated R5-R11)
    const uint32_t a_row  = (uint32_t)(wm * 32 + (lane & 15));
    const uint32_t a_byte = (uint32_t)((lane >> 4) << 4);
    const uint32_t b_row  = (uint32_t)(wn * 32 + (lane & 7) + ((lane >> 4) << 3));
    const uint32_t b_byte = (uint32_t)((lane & 8) << 1);

    load_chunk(0);

    for (int c = 0; c < NC; c++) {
        if (c + 1 < NC) load_chunk(c + 1);
        if (c + 1 < NC) asm volatile("cp.async.wait_group 1;\n" ::: "memory");
        else            asm volatile("cp.async.wait_group 0;\n" ::: "memory");
        __syncthreads();

        const uint32_t stage = sb + (uint32_t)(c & 1) * STAGE_B;
        const uint32_t aB0 = stage;
        const uint32_t bB0 = stage + A_TILE_B;

        #pragma unroll
        for (int ks = 0; ks < 4; ks++) {
            const uint32_t kb = (uint32_t)ks * 32;
            uint32_t a0f[2][4];
            #pragma unroll
            for (int mt = 0; mt < 2; mt++) {
                uint32_t off = swz((a_row + mt * 16) * 128 + kb + a_byte);
                LDSM4(a0f[mt][0], a0f[mt][1], a0f[mt][2], a0f[mt][3], aB0 + off);
            }
            uint32_t b0f[2][4];
            #pragma unroll
            for (int nt = 0; nt < 2; nt++) {
                uint32_t off = swz((b_row + nt * 16) * 128 + kb + b_byte);
                LDSM4(b0f[nt][0], b0f[nt][1], b0f[nt][2], b0f[nt][3], bB0 + off);
            }
            #pragma unroll
            for (int mt = 0; mt < 2; mt++) {
                #pragma unroll
                for (int nt = 0; nt < 2; nt++) {
                    MMAH(acc[mt][2 * nt],     a0f[mt], b0f[nt][0], b0f[nt][1]);
                    MMAH(acc[mt][2 * nt + 1], a0f[mt], b0f[nt][2], b0f[nt][3]);
                }
            }
        }
        __syncthreads();
    }

    // epilogue: fragment thread t holds rows {t/4, t/4+8}, cols {2(t%4), +1}
    float2 bias[4];
    {
        const int nbase = n0 + wn * 32 + 2 * (lane & 3);
        #pragma unroll
        for (int nt8 = 0; nt8 < 4; nt8++) {
            bias[nt8].x = bih[nbase + nt8 * 8];
            bias[nt8].y = bih[nbase + nt8 * 8 + 1];
        }
    }
    #pragma unroll
    for (int mt = 0; mt < 2; mt++) {
        const int mlo = m0 + wm * 32 + mt * 16 + (lane >> 2);
        #pragma unroll
        for (int nt8 = 0; nt8 < 4; nt8++) {
            const int n = n0 + wn * 32 + nt8 * 8 + 2 * (lane & 3);
            float2 lo, hi;
            lo.x = acc[mt][nt8][0] + bias[nt8].x;
            lo.y = acc[mt][nt8][1] + bias[nt8].y;
            hi.x = acc[mt][nt8][2] + bias[nt8].x;
            hi.y = acc[mt][nt8][3] + bias[nt8].y;
            *(float2*)(g_gi + (size_t)mlo * NGI + n)       = lo;
            *(float2*)(g_gi + (size_t)(mlo + 8) * NGI + n) = hi;
        }
    }
}

// =====================================================================
// Kernel 4: persistent GRU (R7 shape: 256 thr, W_hh in registers,
// GLOBAL barrier). 128 CTAs = 8 bt x 16 jt. gi PREFETCHED across the
// barrier (loads for t+1 issued before the barrier arrival); tight
// spin (no nanosleep) on the release flag.
// =====================================================================
#define GRU_CTAS   128

__global__ __launch_bounds__(256, 1) void gru_persist(
    const float* __restrict__ Whh,   // (768,256)
    const float* __restrict__ bhh,   // (768)
    const float* __restrict__ Wout,  // (10,256)
    const float* __restrict__ bout,  // (10)
    float* __restrict__ out)         // (128,10)
{
    // hs[b][i4][kc][4] : element k of row b at ((b*4 + (k>>2)&3)*16 + k>>4)*4 + (k&3)
    __shared__ __align__(16) float hs[4096];   // 16 KB

    const int tid  = threadIdx.x;
    const int w    = tid >> 5;
    const int lane = tid & 31;
    const int jj   = lane >> 4;
    const int kc   = lane & 15;
    const int bt = blockIdx.x >> 4, jt = blockIdx.x & 15;
    const int b0 = bt * 16, j0 = jt * 16;
    const int j  = j0 + (w << 1) + jj;   // this lane's gate column
    const int b  = b0 + kc;              // this lane's output batch row

    // ---- one-time: W_hh[3 gates][my 16-k slice] -> registers ----
    float4 W4[3][4];
    #pragma unroll
    for (int g = 0; g < 3; g++)
        #pragma unroll
        for (int i4 = 0; i4 < 4; i4++)
            W4[g][i4] = *(const float4*)&Whh[(g * RNN_ + j) * RNN_ + kc * 16 + i4 * 4];

    const float br = bhh[j], bz = bhh[RNN_ + j], bn = bhh[2 * RNN_ + j];
    // h_prev smem index for (b=kc row, col j)
    const int hprev_idx = ((kc * 4 + ((j >> 2) & 3)) * 16 + (j >> 4)) * 4 + (j & 3);

    // prefetch gi for t=0 (GEMM already complete)
    float ir, iz, inn;
    {
        const float* gi0 = g_gi + (size_t)b * NGI;
        ir  = __ldcg(&gi0[j]);
        iz  = __ldcg(&gi0[RNN_ + j]);
        inn = __ldcg(&gi0[2 * RNN_ + j]);
    }

    for (int t = 0; t < W_; t++) {
        // ---- fill hs (swizzled) ----
        if (t == 0) {
            #pragma unroll
            for (int i = tid; i < 1024; i += 256)
                *(float4*)&hs[i * 4] = make_float4(0.f, 0.f, 0.f, 0.f);
        } else {
            const float* hi = g_h[t & 1];
            #pragma unroll
            for (int i = tid; i < 1024; i += 256) {
                int bb = i >> 6, q = i & 63;         // q = k/4
                int kcs = q >> 2, i4 = q & 3;
                float4 v = __ldcg((const float4*)&hi[(b0 + bb) * RNN_ + q * 4]);
                *(float4*)&hs[((bb * 4 + i4) * 16 + kcs) * 4] = v;
            }
        }
        __syncthreads();

        // ---- partials: all 16 b-rows over my 16-k slice ----
        float acc[16][3];
        #pragma unroll
        for (int bb = 0; bb < 16; bb++) {
            float4 h0 = *(const float4*)&hs[((bb * 4 + 0) * 16 + kc) * 4];
            float4 h1 = *(const float4*)&hs[((bb * 4 + 1) * 16 + kc) * 4];
            float4 h2 = *(const float4*)&hs[((bb * 4 + 2) * 16 + kc) * 4];
            float4 h3 = *(const float4*)&hs[((bb * 4 + 3) * 16 + kc) * 4];
            #pragma unroll
            for (int g = 0; g < 3; g++) {
                float s;
                s  = W4[g][0].x * h0.x + W4[g][0].y * h0.y + W4[g][0].z * h0.z + W4[g][0].w * h0.w;
                s += W4[g][1].x * h1.x + W4[g][1].y * h1.y + W4[g][1].z * h1.z + W4[g][1].w * h1.w;
                s += W4[g][2].x * h2.x + W4[g][2].y * h2.y + W4[g][2].z * h2.z + W4[g][2].w * h2.w;
                s += W4[g][3].x * h3.x + W4[g][3].y * h3.y + W4[g][3].z * h3.z + W4[g][3].w * h3.w;
                acc[bb][g] = s;
            }
        }

        // ---- transpose-butterfly reduce over 16 kc-lanes (45 SHFL) ----
        #pragma unroll
        for (int m = 8; m >= 1; m >>= 1) {
            #pragma unroll
            for (int bb = 0; bb < m; bb++) {
                #pragma unroll
                for (int g = 0; g < 3; g++) {
                    float lo = acc[bb][g], hi2 = acc[bb + m][g];
                    float send = (kc & m) ? lo  : hi2;
                    float keep = (kc & m) ? hi2 : lo;
                    acc[bb][g] = keep + __shfl_xor_sync(0xffffffffu, send, m);
                }
            }
        }

        // ---- gates for (b, j) ----
        float r = 1.f / (1.f + expf(-(ir + acc[0][0] + br)));
        float z = 1.f / (1.f + expf(-(iz + acc[0][1] + bz)));
        float n = tanhf(inn + r * (acc[0][2] + bn));
        float hprev = hs[hprev_idx];
        g_h[(t + 1) & 1][b * RNN_ + j] = (1.f - z) * n + z * hprev;

        // ---- prefetch gi for t+1 BEFORE the barrier (hidden latency) ----
        if (t + 1 < W_) {
            const float* gin = g_gi + ((size_t)(t + 1) * B_ + b) * NGI;
            ir  = __ldcg(&gin[j]);
            iz  = __ldcg(&gin[RNN_ + j]);
            inn = __ldcg(&gin[2 * RNN_ + j]);
        }

        // ---- global grid barrier (tight spin) ----
        __threadfence();
        __syncthreads();
        if (tid == 0) {
            unsigned gen = g_bar_gen;
            if (atomicAdd(&g_bar_cnt, 1u) == GRU_CTAS - 1) {
                g_bar_cnt = 0;
                __threadfence();
                g_bar_gen = gen + 1;
            } else {
                while (g_bar_gen == gen) { }
            }
        }
        __syncthreads();
    }

    // ---- output head: 8 CTAs (jt==0), 16 b-rows x 10 outputs each ----
    if (jt == 0) {
        const float* hf = g_h[W_ & 1];   // final h after 31 steps
        for (int i = tid; i < 16 * OUT_; i += 256) {
            int bb = b0 + i / OUT_, o = i % OUT_;
            float s = 0.f;
            #pragma unroll 8
            for (int k = 0; k < RNN_; k += 4) {
                float4 h4 = __ldcg((const float4*)&hf[bb * RNN_ + k]);
                float4 w4 = *(const float4*)&Wout[o * RNN_ + k];
                s += h4.x * w4.x + h4.y * w4.y + h4.z * w4.z + h4.w * w4.w;
            }
            out[bb * OUT_ + o] = 1.f / (1.f + expf(-(s + bout[o])));
        }
    }
}

// =====================================================================
extern "C" void kernel_launch(void* const* d_in, const int* in_sizes, int n_in,
                              void* d_out, int out_size)
{
    const float* x     = (const float*)d_in[0];
    const float* W_aug = (const float*)d_in[1];
    // d_in[2] = b_aug: constant, cancels in increments
    const float* W_ih  = (const float*)d_in[3];
    const float* W_hh  = (const float*)d_in[4];
    const float* b_ih  = (const float*)d_in[5];
    const float* b_hh  = (const float*)d_in[6];
    const float* W_out = (const float*)d_in[7];
    const float* b_out = (const float*)d_in[8];
    float* out = (float*)d_out;

    cudaFuncSetAttribute(gemm_mma, cudaFuncAttributeMaxDynamicSharedMemorySize, GEMM_SMEM);

    sig_kernel<<<dim3(W_, B_ * G_), 128>>>(x, W_aug);
    prep_w<<<(NGI * KP2 + 255) / 256, 256>>>(W_ih);
    gemm_mma<<<dim3(MROWS / 64, NGI / 128), 256, GEMM_SMEM>>>(b_ih);
    gru_persist<<<GRU_CTAS, 256>>>(W_hh, b_hh, W_out, b_out, out);
}

// round 13
// speedup vs baseline: 1.7318x; 1.2303x over previous
#include <cuda_runtime.h>
#include <cuda_fp16.h>
#include <math.h>
#include <stdint.h>

// ---------------- problem constants ----------------
#define B_      128
#define STREAM_ 512
#define INCH    4
#define EXTRA_  5
#define G_      2
#define STEP_   16
#define SIGC    1110        // C + C^2 + C^3, C=10
#define W_      31          // windows
#define F_      2220        // GROUPS * SIGC
#define RNN_    256
#define OUT_    10
#define KP2     2240        // F_ padded to multiple of 64 (fp16 chunk)
#define MROWS   (W_ * B_)   // 3968
#define NGI     768         // 3 * RNN
#define NC      (KP2 / 64)  // 35 K-chunks of 64 fp16 (128 bytes)

// ---------------- device scratch (static, allowed) ----------------
__device__ __half g_A0[MROWS * KP2];          // sig fp16 (~17.8 MB)
__device__ __half g_B0[NGI * KP2];            // W_ih fp16 (~3.4 MB)
__device__ float g_gi[MROWS * NGI];           // [t][b][gate] (~12 MB)
__device__ float g_h [2][B_ * RNN_];          // ping-pong hidden state

// global grid barrier (gen monotonic across graph replays)
__device__ volatile unsigned g_bar_gen;
__device__ unsigned g_bar_cnt;

// ---------------- PTX helpers (portable: sm_80/90 class only) ----------------
__device__ __forceinline__ uint32_t smem_u32(const void* p) {
    uint32_t a;
    asm("{ .reg .u64 t; cvta.to.shared.u64 t, %1; cvt.u32.u64 %0, t; }" : "=r"(a) : "l"(p));
    return a;
}

__device__ __forceinline__ uint32_t swz(uint32_t off) { return off ^ ((off >> 3) & 0x70); }

#define LDSM4(r0, r1, r2, r3, addr)                                               \
    asm volatile("ldmatrix.sync.aligned.m8n8.x4.shared.b16 {%0,%1,%2,%3}, [%4];"  \
        : "=r"(r0), "=r"(r1), "=r"(r2), "=r"(r3) : "r"(addr))

// D += A(16x16) * B(16x8), fp16 in, fp32 accum. row.col = both K-contiguous.
#define MMAH(d, a, b0v, b1v)                                                      \
    asm volatile("mma.sync.aligned.m16n8k16.row.col.f32.f16.f16.f32 "             \
        "{%0,%1,%2,%3}, {%4,%5,%6,%7}, {%8,%9}, {%0,%1,%2,%3};"                   \
        : "+f"((d)[0]), "+f"((d)[1]), "+f"((d)[2]), "+f"((d)[3])                  \
        : "r"((a)[0]), "r"((a)[1]), "r"((a)[2]), "r"((a)[3]), "r"(b0v), "r"(b1v))

__device__ __forceinline__ uint32_t pack_h2(float a, float b) {
    __half2 h = __halves2half2(__float2half_rn(a), __float2half_rn(b));
    return *(uint32_t*)&h;
}

// =====================================================================
// Kernel 1: path signatures (Chen, depth 3) -> fp16 (single-rounded)
// =====================================================================
__global__ __launch_bounds__(128) void sig_kernel(
    const float* __restrict__ x,       // (128,512,4)
    const float* __restrict__ W_aug)   // (2,5,4)
{
    const int w  = blockIdx.x;
    const int bg = blockIdx.y;
    const int b  = bg >> 1;
    const int g  = bg & 1;
    const int tid = threadIdx.x;

    __shared__ __align__(16) float xs[32][4];
    __shared__ __align__(16) float dxw[31][10];

    {
        int row = tid >> 2, ch = tid & 3;
        xs[row][ch] = x[(b * STREAM_ + w * STEP_ + row) * INCH + ch];
    }
    __syncthreads();

    for (int idx = tid; idx < 31 * 10; idx += 128) {
        int j = idx / 10, c = idx % 10;
        float v;
        if (c < 4) {
            v = xs[j + 1][c] - xs[j][c];
        } else if (c == 4) {
            v = 1.0f / 511.0f;
        } else {
            int e = c - 5;
            const float* wa = W_aug + (g * EXTRA_ + e) * INCH;
            v = 0.f;
            #pragma unroll
            for (int i = 0; i < 4; i++) v += wa[i] * (xs[j + 1][i] - xs[j][i]);
        }
        dxw[j][c] = v;
    }
    __syncthreads();

    const size_t base = (size_t)(w * B_ + b) * KP2 + (size_t)g * SIGC;

    if (tid < 100) {
        const int a  = tid / 10;
        const int bb = tid % 10;
        float s1a = 0.f, s2 = 0.f;
        float s3[10];
        #pragma unroll
        for (int c = 0; c < 10; c++) s3[c] = 0.f;

        for (int j = 0; j < 31; j++) {
            float dxa = dxw[j][a];
            float dxb = dxw[j][bb];
            float factor = s2 + dxb * (0.5f * s1a + (1.0f / 6.0f) * dxa);
            #pragma unroll
            for (int c = 0; c < 10; c++) s3[c] += factor * dxw[j][c];
            s2  += dxb * (s1a + 0.5f * dxa);
            s1a += dxa;
        }
        if (bb == 0) g_A0[base + a] = __float2half_rn(s1a);
        g_A0[base + 10 + tid] = __float2half_rn(s2);
        #pragma unroll
        for (int c = 0; c < 10; c++)
            g_A0[base + 110 + tid * 10 + c] = __float2half_rn(s3[c]);
    }
    // zero K-pad columns (g==1 block handles it once per row)
    if (g == 1 && tid < (KP2 - F_))
        g_A0[(size_t)(w * B_ + b) * KP2 + F_ + tid] = __float2half_rn(0.f);
}

// =====================================================================
// Kernel 2: round+pad W_ih (768 x 2220) into g_B0 (768 x 2240) fp16
// =====================================================================
__global__ __launch_bounds__(256) void prep_w(const float* __restrict__ Wih)
{
    int idx = blockIdx.x * 256 + threadIdx.x;
    if (idx < NGI * KP2) {
        int n = idx / KP2, k = idx - n * KP2;
        float v = (k < F_) ? Wih[n * F_ + k] : 0.f;
        g_B0[idx] = __float2half_rn(v);
    }
}

// =====================================================================
// Kernel 3: GI = sig @ W_ih^T + b_ih, SINGLE-product fp16 mma.sync.
// 64x128 CTA tile (372 CTAs, 2/SM), 8 warps of 32(M)x32(N).
// =====================================================================
#define A_TILE_B    8192                   // 64 rows x 128 bytes
#define B_TILE_B    16384                  // 128 rows x 128 bytes
#define STAGE_B     (A_TILE_B + B_TILE_B)  // 24576
#define GEMM_SMEM   (2 * STAGE_B)          // 49152 bytes (2 stages)

__global__ __launch_bounds__(256, 2) void gemm_mma(const float* __restrict__ bih)
{
    extern __shared__ char smem[];
    const uint32_t sb = smem_u32(smem);
    const int tid  = threadIdx.x;
    const int lane = tid & 31;
    const int wid  = tid >> 5;
    const int wm   = wid & 1;         // M offset 32*wm
    const int wn   = wid >> 1;        // 0..3 -> N offset 32*wn
    const int m0 = blockIdx.x * 64;
    const int n0 = blockIdx.y * 128;

    const __half* aA0  = g_A0 + (size_t)m0 * KP2;
    const __half* bB0g = g_B0 + (size_t)n0 * KP2;

    auto load_chunk = [&](int c) {
        uint32_t sbase = sb + (uint32_t)(c & 1) * STAGE_B;
        #pragma unroll
        for (int it = 0; it < 2; it++) {
            int i = tid + it * 256;               // 0..511
            int row = i >> 3, seg = i & 7;
            uint32_t dst = sbase + swz((uint32_t)row * 128 + (uint32_t)seg * 16);
            const void* src = aA0 + (size_t)row * KP2 + (size_t)c * 64 + seg * 8;
            asm volatile("cp.async.cg.shared.global [%0], [%1], 16;\n"
                         :: "r"(dst), "l"(src));
        }
        #pragma unroll
        for (int it = 0; it < 4; it++) {
            int i = tid + it * 256;               // 0..1023
            int row = i >> 3, seg = i & 7;
            uint32_t dst = sbase + A_TILE_B
                         + swz((uint32_t)row * 128 + (uint32_t)seg * 16);
            const void* src = bB0g + (size_t)row * KP2 + (size_t)c * 64 + seg * 8;
            asm volatile("cp.async.cg.shared.global [%0], [%1], 16;\n"
                         :: "r"(dst), "l"(src));
        }
        asm volatile("cp.async.commit_group;\n" ::: "memory");
    };

    float acc[2][4][4];
    #pragma unroll
    for (int i = 0; i < 2; i++)
        #pragma unroll
        for (int jj = 0; jj < 4; jj++)
            #pragma unroll
            for (int k = 0; k < 4; k++) acc[i][jj][k] = 0.f;

    const uint32_t a_row  = (uint32_t)(wm * 32 + (lane & 15));
    const uint32_t a_byte = (uint32_t)((lane >> 4) << 4);
    const uint32_t b_row  = (uint32_t)(wn * 32 + (lane & 7) + ((lane >> 4) << 3));
    const uint32_t b_byte = (uint32_t)((lane & 8) << 1);

    load_chunk(0);

    for (int c = 0; c < NC; c++) {
        if (c + 1 < NC) load_chunk(c + 1);
        if (c + 1 < NC) asm volatile("cp.async.wait_group 1;\n" ::: "memory");
        else            asm volatile("cp.async.wait_group 0;\n" ::: "memory");
        __syncthreads();

        const uint32_t stage = sb + (uint32_t)(c & 1) * STAGE_B;
        const uint32_t aB0 = stage;
        const uint32_t bB0 = stage + A_TILE_B;

        #pragma unroll
        for (int ks = 0; ks < 4; ks++) {
            const uint32_t kb = (uint32_t)ks * 32;
            uint32_t a0f[2][4];
            #pragma unroll
            for (int mt = 0; mt < 2; mt++) {
                uint32_t off = swz((a_row + mt * 16) * 128 + kb + a_byte);
                LDSM4(a0f[mt][0], a0f[mt][1], a0f[mt][2], a0f[mt][3], aB0 + off);
            }
            uint32_t b0f[2][4];
            #pragma unroll
            for (int nt = 0; nt < 2; nt++) {
                uint32_t off = swz((b_row + nt * 16) * 128 + kb + b_byte);
                LDSM4(b0f[nt][0], b0f[nt][1], b0f[nt][2], b0f[nt][3], bB0 + off);
            }
            #pragma unroll
            for (int mt = 0; mt < 2; mt++) {
                #pragma unroll
                for (int nt = 0; nt < 2; nt++) {
                    MMAH(acc[mt][2 * nt],     a0f[mt], b0f[nt][0], b0f[nt][1]);
                    MMAH(acc[mt][2 * nt + 1], a0f[mt], b0f[nt][2], b0f[nt][3]);
                }
            }
        }
        __syncthreads();
    }

    float2 bias[4];
    {
        const int nbase = n0 + wn * 32 + 2 * (lane & 3);
        #pragma unroll
        for (int nt8 = 0; nt8 < 4; nt8++) {
            bias[nt8].x = bih[nbase + nt8 * 8];
            bias[nt8].y = bih[nbase + nt8 * 8 + 1];
        }
    }
    #pragma unroll
    for (int mt = 0; mt < 2; mt++) {
        const int mlo = m0 + wm * 32 + mt * 16 + (lane >> 2);
        #pragma unroll
        for (int nt8 = 0; nt8 < 4; nt8++) {
            const int n = n0 + wn * 32 + nt8 * 8 + 2 * (lane & 3);
            float2 lo, hi;
            lo.x = acc[mt][nt8][0] + bias[nt8].x;
            lo.y = acc[mt][nt8][1] + bias[nt8].y;
            hi.x = acc[mt][nt8][2] + bias[nt8].x;
            hi.y = acc[mt][nt8][3] + bias[nt8].y;
            *(float2*)(g_gi + (size_t)mlo * NGI + n)       = lo;
            *(float2*)(g_gi + (size_t)(mlo + 8) * NGI + n) = hi;
        }
    }
}

// =====================================================================
// Kernel 4: persistent GRU v4 — gh via tensor cores (exact fp16-pair
// split of h; W pre-split into register B-fragments). 128 CTAs =
// 8 bt x 16 jt, 256 threads (8 warps; warps 0-5 own one n8 block of
// the 48 gate columns padded to 64). Per step: h -> (h0,h1) fp16 in
// smem; 16 x (2 LDSM + 3 MMA) per warp (h0W0+h0W1+h1W0, h1W1 ~2^-22
// dropped); gates combined through a small smem exchange.
// =====================================================================
#define GRU_CTAS   128
#define HROWH      264      // 256 + 8 halves pad (conflict-free LDSM)

__global__ __launch_bounds__(256, 1) void gru_persist(
    const float* __restrict__ Whh,   // (768,256)
    const float* __restrict__ bhh,   // (768)
    const float* __restrict__ Wout,  // (10,256)
    const float* __restrict__ bout,  // (10)
    float* __restrict__ out)         // (128,10)
{
    __shared__ __align__(16) __half hs0[16][HROWH];   // 8.25 KB
    __shared__ __align__(16) __half hs1[16][HROWH];
    __shared__ __align__(16) float  ghs[16][66];      // 4.1 KB

    const int tid  = threadIdx.x;
    const int w    = tid >> 5;
    const int lane = tid & 31;
    const int bt = blockIdx.x >> 4, jt = blockIdx.x & 15;
    const int b0 = bt * 16, j0 = jt * 16;

    // this thread's gate-output assignment (independent of warp role)
    const int obb = tid >> 4, ojl = tid & 15;
    const int ob  = b0 + obb, oj = j0 + ojl;
    const float br = bhh[oj], bz = bhh[RNN_ + oj], bn = bhh[2 * RNN_ + oj];

    // ---- one-time: W_hh B-fragments (W0 + residual W1) in registers ----
    // warp w (<6) owns gate columns colg = 8w..8w+7 (of 48); B-frag lane
    // map: n = lane>>2, k = 2*(lane&3) + {0,1} (+8 for second reg).
    const bool active = (w < 6);
    uint32_t WF0[16][2], WF1[16][2];
    if (active) {
        const int colg = 8 * w + (lane >> 2);            // 0..47
        const int jrow = (colg >> 4) * RNN_ + j0 + (colg & 15);
        const float* wr = Whh + (size_t)jrow * RNN_;
        const int k2 = (lane & 3) * 2;
        #pragma unroll
        for (int ks = 0; ks < 16; ks++) {
            const int kb = ks * 16 + k2;
            float v0 = wr[kb], v1 = wr[kb + 1], v8 = wr[kb + 8], v9 = wr[kb + 9];
            __half h0 = __float2half_rn(v0), h1 = __float2half_rn(v1);
            __half h8 = __float2half_rn(v8), h9 = __float2half_rn(v9);
            WF0[ks][0] = pack_h2(v0, v1);   // rn of v0,v1
            WF0[ks][1] = pack_h2(v8, v9);
            WF1[ks][0] = pack_h2(v0 - __half2float(h0), v1 - __half2float(h1));
            WF1[ks][1] = pack_h2(v8 - __half2float(h8), v9 - __half2float(h9));
        }
    }

    // prefetch gi for t=0
    float ir, iz, inn;
    {
        const float* gi0 = g_gi + (size_t)ob * NGI;
        ir  = __ldcg(&gi0[oj]);
        iz  = __ldcg(&gi0[RNN_ + oj]);
        inn = __ldcg(&gi0[2 * RNN_ + oj]);
    }

    const uint32_t hb0 = smem_u32(&hs0[0][0]);
    const uint32_t hb1 = smem_u32(&hs1[0][0]);
    // ldmatrix A per-lane: row = lane&15, +16B for k-hi half
    const uint32_t aoff_base = (uint32_t)(lane & 15) * (HROWH * 2)
                             + (uint32_t)((lane >> 4) << 4);

    for (int t = 0; t < W_; t++) {
        // ---- fill hs0/hs1 with exact fp16 split of h_t (zeros at t=0) ----
        if (t == 0) {
            for (int i = tid; i < 16 * HROWH / 2; i += 256) {
                ((uint32_t*)hs0)[i] = 0u;
                ((uint32_t*)hs1)[i] = 0u;
            }
        } else {
            const float* hi = g_h[t & 1];
            const int row = tid >> 4, cb = (tid & 15) * 16;
            const float* src = &hi[(b0 + row) * RNN_ + cb];
            float v[16];
            #pragma unroll
            for (int q = 0; q < 4; q++)
                *(float4*)&v[q * 4] = __ldcg((const float4*)&src[q * 4]);
            uint32_t p0[8], p1[8];
            #pragma unroll
            for (int e = 0; e < 8; e++) {
                float a = v[2 * e], bvl = v[2 * e + 1];
                __half ha = __float2half_rn(a), hbv = __float2half_rn(bvl);
                p0[e] = pack_h2(a, bvl);
                p1[e] = pack_h2(a - __half2float(ha), bvl - __half2float(hbv));
            }
            uint32_t* d0 = (uint32_t*)&hs0[row][cb];
            uint32_t* d1 = (uint32_t*)&hs1[row][cb];
            *(uint4*)&d0[0] = *(uint4*)&p0[0];
            *(uint4*)&d0[4] = *(uint4*)&p0[4];
            *(uint4*)&d1[0] = *(uint4*)&p1[0];
            *(uint4*)&d1[4] = *(uint4*)&p1[4];
        }
        __syncthreads();

        // ---- MMA: gh[16][8] per active warp, K=256 ----
        if (active) {
            float C[4] = {0.f, 0.f, 0.f, 0.f};
            #pragma unroll
            for (int ks = 0; ks < 16; ks++) {
                const uint32_t off = aoff_base + (uint32_t)ks * 32;
                uint32_t A0[4], A1[4];
                LDSM4(A0[0], A0[1], A0[2], A0[3], hb0 + off);
                LDSM4(A1[0], A1[1], A1[2], A1[3], hb1 + off);
                MMAH(C, A0, WF0[ks][0], WF0[ks][1]);
                MMAH(C, A0, WF1[ks][0], WF1[ks][1]);
                MMAH(C, A1, WF0[ks][0], WF0[ks][1]);
            }
            const int r = lane >> 2, cc = 8 * w + 2 * (lane & 3);
            ghs[r][cc]         = C[0];
            ghs[r][cc + 1]     = C[1];
            ghs[r + 8][cc]     = C[2];
            ghs[r + 8][cc + 1] = C[3];
        }
        __syncthreads();

        // ---- gates for (ob, oj) ----
        float hr  = ghs[obb][ojl];
        float hz  = ghs[obb][16 + ojl];
        float hn3 = ghs[obb][32 + ojl];
        float hprev = __half2float(hs0[obb][oj]) + __half2float(hs1[obb][oj]);
        float r_ = 1.f / (1.f + expf(-(ir + hr + br)));
        float z_ = 1.f / (1.f + expf(-(iz + hz + bz)));
        float n_ = tanhf(inn + r_ * (hn3 + bn));
        g_h[(t + 1) & 1][ob * RNN_ + oj] = (1.f - z_) * n_ + z_ * hprev;

        // prefetch gi for t+1 before the barrier
        if (t + 1 < W_) {
            const float* gin = g_gi + ((size_t)(t + 1) * B_ + ob) * NGI;
            ir  = __ldcg(&gin[oj]);
            iz  = __ldcg(&gin[RNN_ + oj]);
            inn = __ldcg(&gin[2 * RNN_ + oj]);
        }

        // ---- global grid barrier ----
        __threadfence();
        __syncthreads();
        if (tid == 0) {
            unsigned gen = g_bar_gen;
            if (atomicAdd(&g_bar_cnt, 1u) == GRU_CTAS - 1) {
                g_bar_cnt = 0;
                __threadfence();
                g_bar_gen = gen + 1;
            } else {
                while (g_bar_gen == gen) __nanosleep(32);
            }
        }
        __syncthreads();
    }

    // ---- output head: 8 CTAs (jt==0), 16 b-rows x 10 outputs each ----
    if (jt == 0) {
        const float* hf = g_h[W_ & 1];   // final h after 31 steps
        for (int i = tid; i < 16 * OUT_; i += 256) {
            int bb = b0 + i / OUT_, o = i % OUT_;
            float s = 0.f;
            #pragma unroll 8
            for (int k = 0; k < RNN_; k += 4) {
                float4 h4 = __ldcg((const float4*)&hf[bb * RNN_ + k]);
                float4 w4 = *(const float4*)&Wout[o * RNN_ + k];
                s += h4.x * w4.x + h4.y * w4.y + h4.z * w4.z + h4.w * w4.w;
            }
            out[bb * OUT_ + o] = 1.f / (1.f + expf(-(s + bout[o])));
        }
    }
}

// =====================================================================
extern "C" void kernel_launch(void* const* d_in, const int* in_sizes, int n_in,
                              void* d_out, int out_size)
{
    const float* x     = (const float*)d_in[0];
    const float* W_aug = (const float*)d_in[1];
    // d_in[2] = b_aug: constant, cancels in increments
    const float* W_ih  = (const float*)d_in[3];
    const float* W_hh  = (const float*)d_in[4];
    const float* b_ih  = (const float*)d_in[5];
    const float* b_hh  = (const float*)d_in[6];
    const float* W_out = (const float*)d_in[7];
    const float* b_out = (const float*)d_in[8];
    float* out = (float*)d_out;

    cudaFuncSetAttribute(gemm_mma, cudaFuncAttributeMaxDynamicSharedMemorySize, GEMM_SMEM);

    sig_kernel<<<dim3(W_, B_ * G_), 128>>>(x, W_aug);
    prep_w<<<(NGI * KP2 + 255) / 256, 256>>>(W_ih);
    gemm_mma<<<dim3(MROWS / 64, NGI / 128), 256, GEMM_SMEM>>>(b_ih);
    gru_persist<<<GRU_CTAS, 256>>>(W_hh, b_hh, W_out, b_out, out);
}